// round 11
// baseline (speedup 1.0000x reference)
#include <cuda_runtime.h>
#include <math.h>
#include <mma.h>

using namespace nvcuda;

// ---------------- sizes ----------------
#define BATCH 16
#define H0 256
#define W0 256
#define CIN 3
#define HID 128
#define EMB 64
#define KCODES 1024
#define H1v 128
#define W1v 128
#define H2v 64
#define W2v 64

#define XREC_ELEMS (BATCH*H0*W0*3)      // 3145728
#define TOK_OFF    XREC_ELEMS
#define TOK_ELEMS  (BATCH*H2v*W2v)      // 65536
#define LOSS_OFF   (TOK_OFF + TOK_ELEMS)

typedef unsigned long long u64;
typedef unsigned int u32;

// ---------------- scratch ----------------
__device__ float g_h1[BATCH*H1v*W1v*HID];   // encoder conv1 out (gelu'd)
__device__ float g_ze[BATCH*H2v*W2v*EMB];   // z_e
__device__ float g_zst[BATCH*H2v*W2v*EMB];  // z_st (tf32-rounded at producer)
__device__ float g_g1[BATCH*H1v*W1v*HID];   // decoder convt1 out (gelu'd, tf32-rounded)
__device__ float g_wt1[1024*128];           // dec_w1 tf32-rounded
__device__ float g_wt2[2048*128];           // dec_w2 tf32-rounded
__device__ float g_loss;

__device__ __forceinline__ float gelu_f(float x) {
    float t = 0.7978845608028654f * (x + 0.044715f * x * x * x);
    return 0.5f * x * (1.0f + tanhf(t));
}
__device__ __forceinline__ float tf32r(float x) { return wmma::__float_to_tf32(x); }

// ---------------- packed f32x2 helpers ----------------
__device__ __forceinline__ u64 splat2(float a) {
    u64 r; asm("mov.b64 %0, {%1, %1};" : "=l"(r) : "f"(a)); return r;
}
__device__ __forceinline__ u64 pack2(float lo, float hi) {
    u64 r; asm("mov.b64 %0, {%1, %2};" : "=l"(r) : "f"(lo), "f"(hi)); return r;
}
__device__ __forceinline__ void unpack2(u64 v, float& lo, float& hi) {
    asm("mov.b64 {%0, %1}, %2;" : "=f"(lo), "=f"(hi) : "l"(v));
}
__device__ __forceinline__ void ffma2(u64& d, u64 a, u64 b) {
    asm("fma.rn.f32x2 %0, %1, %2, %0;" : "+l"(d) : "l"(a), "l"(b));
}
#define FFMA2_8(J, AJ) { u64 s_ = splat2(AJ); \
    ffma2(acc2[J][0], s_, w01); ffma2(acc2[J][1], s_, w23); \
    ffma2(acc2[J][2], s_, w45); ffma2(acc2[J][3], s_, w67); }

// ---------------- cp.async ----------------
__device__ __forceinline__ void cp16z(float* sdst, const float* gsrc, u32 srcsz) {
    u32 sa = (u32)__cvta_generic_to_shared(sdst);
    asm volatile("cp.async.cg.shared.global [%0], [%1], 16, %2;"
                 :: "r"(sa), "l"(gsrc), "r"(srcsz));
}
#define CPA_COMMIT() asm volatile("cp.async.commit_group;")

// ================= prep: tf32 round =================
__global__ void k_prep_tf32(const float* __restrict__ w, float* __restrict__ o, int n) {
    int i = blockIdx.x * 256 + threadIdx.x;
    if (i < n) o[i] = tf32r(w[i]);
}

// ================= conv1: x -> h1, 4x4 s2 SAME, gelu (fp32) =================
__global__ void k_conv1(const float* __restrict__ x, const float* __restrict__ w,
                        const float* __restrict__ b) {
    __shared__ float ws[4*4*3*128];
    __shared__ float ins[4*34*3];
    int tid = threadIdx.x;
    int bx = blockIdx.x, oy = blockIdx.y, n = blockIdx.z;
    if (bx == 0 && oy == 0 && n == 0 && tid == 0) g_loss = 0.0f;
    for (int i = tid; i < 6144; i += 128) ws[i] = w[i];
    int x0 = bx * 16;
    for (int i = tid; i < 4*34*3; i += 128) {
        int r = i / (34*3); int rem = i - r*(34*3); int c = rem / 3; int ch = rem % 3;
        int gy = 2*oy - 1 + r;
        int gx = 2*x0 - 1 + c;
        float v = 0.0f;
        if (gy >= 0 && gy < H0 && gx >= 0 && gx < W0) v = x[((n*H0+gy)*W0+gx)*CIN + ch];
        ins[i] = v;
    }
    __syncthreads();
    int co = tid;
    float bias = b[co];
    u64 acc2[8];
#pragma unroll
    for (int pp = 0; pp < 8; pp++) acc2[pp] = pack2(bias, bias);
    for (int ky = 0; ky < 4; ky++) {
        for (int kx = 0; kx < 4; kx++) {
#pragma unroll
            for (int ci = 0; ci < 3; ci++) {
                float wv = ws[((ky*4+kx)*3+ci)*128 + co];
                u64 wvv = splat2(wv);
#pragma unroll
                for (int pp = 0; pp < 8; pp++) {
                    u64 av = pack2(ins[(ky*34 + 4*pp + kx)*3 + ci],
                                   ins[(ky*34 + 4*pp + 2 + kx)*3 + ci]);
                    ffma2(acc2[pp], av, wvv);
                }
            }
        }
    }
#pragma unroll
    for (int pp = 0; pp < 8; pp++) {
        float v0, v1; unpack2(acc2[pp], v0, v1);
        g_h1[((n*H1v+oy)*W1v + x0 + 2*pp)*HID + co]     = gelu_f(v0);
        g_h1[((n*H1v+oy)*W1v + x0 + 2*pp + 1)*HID + co] = gelu_f(v1);
    }
}

// ================= conv2 (GEMM-tiled, f32x2) + gelu + 1x1: h1 -> z_e =================
__global__ void __launch_bounds__(128) k_conv2(const float* __restrict__ w2, const float* __restrict__ b2,
                                               const float* __restrict__ w3, const float* __restrict__ b3) {
    __shared__ float sm[2112 + 8192];
    float* ins = sm;
    float* Bs  = sm + 2112;
    float* h2s = sm;
    int tid = threadIdx.x;
    int oy = blockIdx.x, n = blockIdx.y;
    int pa = tid & 7, cg = tid >> 3;
    int co0 = cg * 8;
    u64 acc2[8][4];
    {
        float4 b0 = *reinterpret_cast<const float4*>(&b2[co0]);
        float4 b1 = *reinterpret_cast<const float4*>(&b2[co0+4]);
        u64 p0 = pack2(b0.x,b0.y), p1 = pack2(b0.z,b0.w);
        u64 p2 = pack2(b1.x,b1.y), p3 = pack2(b1.z,b1.w);
#pragma unroll
        for (int j = 0; j < 8; j++) { acc2[j][0]=p0; acc2[j][1]=p1; acc2[j][2]=p2; acc2[j][3]=p3; }
    }
    int axbase = 2 * pa;
#pragma unroll 1
    for (int ch = 0; ch < 32; ch++) {
        int ci0 = ch * 4;
        for (int i = tid; i < 520; i += 128) {
            int r = i / 130; int ixl = i - r*130;
            int iy = 2*oy - 1 + r;
            int ix = ixl - 1;
            float4 v = make_float4(0,0,0,0);
            if (iy >= 0 && iy < H1v && ix >= 0 && ix < W1v)
                v = *reinterpret_cast<const float4*>(&g_h1[((n*H1v+iy)*W1v+ix)*HID + ci0]);
            float* dst = &ins[(r*4)*132 + ixl];
            dst[0] = v.x; dst[132] = v.y; dst[264] = v.z; dst[396] = v.w;
        }
        for (int i = tid; i < 2048; i += 128) {
            int co4 = i & 31; int cik = (i >> 5) & 3; int tap = i >> 7;
            float4 wv = *reinterpret_cast<const float4*>(&w2[((tap*HID) + ci0 + cik)*HID + co4*4]);
            *reinterpret_cast<float4*>(&Bs[(tap*4+cik)*128 + co4*4]) = wv;
        }
        __syncthreads();
        for (int tap = 0; tap < 16; tap++) {
            int kx = tap & 3; int row = tap >> 2;
#pragma unroll
            for (int cik = 0; cik < 4; cik++) {
                const u64* bp = reinterpret_cast<const u64*>(&Bs[(tap*4+cik)*128 + co0]);
                u64 w01 = bp[0], w23 = bp[1], w45 = bp[2], w67 = bp[3];
                const float* ap = &ins[(row*4+cik)*132 + axbase + kx];
                float a0 = ap[0],  a1 = ap[16], a2 = ap[32], a3 = ap[48];
                float a4 = ap[64], a5 = ap[80], a6 = ap[96], a7 = ap[112];
                FFMA2_8(0,a0) FFMA2_8(1,a1) FFMA2_8(2,a2) FFMA2_8(3,a3)
                FFMA2_8(4,a4) FFMA2_8(5,a5) FFMA2_8(6,a6) FFMA2_8(7,a7)
            }
        }
        __syncthreads();
    }
#pragma unroll
    for (int j = 0; j < 8; j++) {
        int ox = pa + 8*j;
        float f0,f1,f2,f3,f4,f5,f6,f7;
        unpack2(acc2[j][0], f0, f1); unpack2(acc2[j][1], f2, f3);
        unpack2(acc2[j][2], f4, f5); unpack2(acc2[j][3], f6, f7);
        float4 o0 = make_float4(gelu_f(f0), gelu_f(f1), gelu_f(f2), gelu_f(f3));
        float4 o1 = make_float4(gelu_f(f4), gelu_f(f5), gelu_f(f6), gelu_f(f7));
        *reinterpret_cast<float4*>(&h2s[ox*132 + co0])     = o0;
        *reinterpret_cast<float4*>(&h2s[ox*132 + co0 + 4]) = o1;
    }
    __syncthreads();
    {
        int px = tid >> 1;
        int e0 = (tid & 1) * 32;
        u64 z2[16];
#pragma unroll
        for (int u = 0; u < 8; u++) {
            float4 bb = *reinterpret_cast<const float4*>(&b3[e0 + 4*u]);
            z2[2*u]   = pack2(bb.x, bb.y);
            z2[2*u+1] = pack2(bb.z, bb.w);
        }
#pragma unroll 4
        for (int ci = 0; ci < 128; ci++) {
            float hv = h2s[px*132 + ci];
            u64 s = splat2(hv);
#pragma unroll
            for (int u = 0; u < 8; u++) {
                float4 wv = *reinterpret_cast<const float4*>(&w3[ci*EMB + e0 + 4*u]);
                ffma2(z2[2*u],   s, pack2(wv.x, wv.y));
                ffma2(z2[2*u+1], s, pack2(wv.z, wv.w));
            }
        }
        float* dst = &g_ze[((n*H2v+oy)*W2v + px)*EMB + e0];
#pragma unroll
        for (int u = 0; u < 8; u++) {
            float f0,f1,f2,f3;
            unpack2(z2[2*u], f0, f1); unpack2(z2[2*u+1], f2, f3);
            *reinterpret_cast<float4*>(dst + 4*u) = make_float4(f0, f1, f2, f3);
        }
    }
}

// ================= VQ =================
#define CSTR 68
__global__ void k_vq(const float* __restrict__ cb, float* __restrict__ dout) {
    __shared__ float cs[64*CSTR];
    __shared__ float e2s[64];
    __shared__ float bval[128];
    __shared__ int   bidx[128];
    __shared__ int   widx[16];
    __shared__ float lred[128];
    int tid = threadIdx.x;
    int pb = blockIdx.x * 16;
    int p = tid & 15;
    int g = tid >> 4;
    float4 z4[16];
    const float* zp = &g_ze[(pb + p)*EMB];
#pragma unroll
    for (int i = 0; i < 16; i++) z4[i] = *reinterpret_cast<const float4*>(&zp[4*i]);
    float best = 3.4e38f; int bi = 0;
    for (int ch = 0; ch < 16; ch++) {
        for (int i = tid; i < 64*16; i += 128) {
            int cj = i >> 4; int d4 = i & 15;
            float4 v = *reinterpret_cast<const float4*>(&cb[(ch*64+cj)*EMB + 4*d4]);
            *reinterpret_cast<float4*>(&cs[cj*CSTR + 4*d4]) = v;
        }
        __syncthreads();
        if (tid < 64) {
            float s = 0.0f;
#pragma unroll 8
            for (int d = 0; d < 64; d++) { float c = cs[tid*CSTR + d]; s = fmaf(c, c, s); }
            e2s[tid] = s;
        }
        __syncthreads();
#pragma unroll
        for (int j = 0; j < 8; j++) {
            int cj = g*8 + j;
            const float* cp = &cs[cj*CSTR];
            float dot = 0.0f;
#pragma unroll
            for (int i = 0; i < 16; i++) {
                float4 c = *reinterpret_cast<const float4*>(&cp[4*i]);
                dot = fmaf(z4[i].x, c.x, dot); dot = fmaf(z4[i].y, c.y, dot);
                dot = fmaf(z4[i].z, c.z, dot); dot = fmaf(z4[i].w, c.w, dot);
            }
            float dist = e2s[cj] - 2.0f*dot;
            int gidx = ch*64 + cj;
            if (dist < best || (dist == best && gidx < bi)) { best = dist; bi = gidx; }
        }
        __syncthreads();
    }
    bval[tid] = best; bidx[tid] = bi;
    __syncthreads();
    if (tid < 16) {
        float bb = bval[tid]; int bbi = bidx[tid];
        for (int k = 1; k < 8; k++) {
            float v = bval[tid + 16*k]; int vi = bidx[tid + 16*k];
            if (v < bb || (v == bb && vi < bbi)) { bb = v; bbi = vi; }
        }
        widx[tid] = bbi;
        dout[TOK_OFF + pb + tid] = (float)bbi;
    }
    __syncthreads();
    int idx = widx[p];
    float lsum = 0.0f;
    const float* cq = &cb[idx*EMB + g*8];
    const float* ze = &g_ze[(pb + p)*EMB + g*8];
    float*       zs = &g_zst[(pb + p)*EMB + g*8];
#pragma unroll
    for (int d = 0; d < 8; d++) {
        float zq = cq[d]; float z = ze[d];
        float diff = zq - z;
        zs[d] = tf32r(z + diff);          // pre-round for decoder MMA (same as round-at-staging)
        lsum = fmaf(diff, diff, lsum);
    }
    lred[tid] = lsum;
    __syncthreads();
    for (int s = 64; s > 0; s >>= 1) {
        if (tid < s) lred[tid] += lred[tid + s];
        __syncthreads();
    }
    if (tid == 0) atomicAdd(&g_loss, lred[0]);
}

// ================= WMMA tf32 transposed-conv (cp.async double-buffered) ====
// CTA: one parity tile. M=128 (2 out rows x 64 same-parity px), N=128 co,
// K = 2kyi*2kxi*CI in chunks of 64. 256 threads = 8 warps (4m x 2n). occ 1.
// smem (floats): A0[0,8704) A1[8704,17408) B0[17408,25856) B1[25856,34304)
//                bias[34304,..] w3s b3s. Cs epilogue reuse at 0.
template<int CI, int HIN, int WIN, bool RGB>
__global__ void __launch_bounds__(256, 1) k_convt_wmma(
    const float* __restrict__ src, const float* __restrict__ wt,
    const float* __restrict__ bias,
    const float* __restrict__ w3, const float* __restrict__ b3,
    float* __restrict__ dst)
{
    constexpr int CIC64 = CI / 64;
    constexpr int NCH   = 4 * CIC64;
    constexpr int HOUT  = 2 * HIN;
    constexpr int WOUT  = 2 * WIN;

    extern __shared__ float smf[];
    float* Cs    = smf;             // epilogue reuse: 128*132 = 16896
    float* biass = smf + 34304;     // 128
    float* w3s   = smf + 34432;     // 384
    float* b3s   = smf + 34816;     // 3

    int tid = threadIdx.x;
    int bx = blockIdx.x, pr = blockIdx.y, n = blockIdx.z;
    int t  = bx & 1;
    int xh = bx >> 1;
    int oy = 4*(pr >> 1) + (pr & 1);          // rows oy, oy+2
    int x0 = xh * 128;
    int xhalf = x0 >> 1;
    int kyA = oy & 1;
    int iy0 = (oy + kyA - 2) >> 1;

    for (int i = tid; i < 128; i += 256) biass[i] = bias[i];
    if (RGB) {
        for (int i = tid; i < 384; i += 256) w3s[i] = w3[i];
        if (tid < 3) b3s[tid] = b3[tid];
    }

    int wid = tid >> 5;
    int m0 = (wid & 3) * 32;
    int n0 = (wid >> 2) * 64;

    wmma::fragment<wmma::accumulator, 16, 16, 8, float> acc[2][4];
#pragma unroll
    for (int im = 0; im < 2; im++)
#pragma unroll
        for (int in = 0; in < 4; in++) wmma::fill_fragment(acc[im][in], 0.0f);

    // stage chunk c into buffer b via cp.async
    auto stage = [&](int c, int b) {
        int kyi = c / (2*CIC64);
        int kxi = (c / CIC64) & 1;
        int ci0 = (c % CIC64) * 64;
        float* A = smf + b * 8704;
        float* B = smf + 17408 + b * 8448;
        int xb = xhalf + t + kxi - 1;
#pragma unroll
        for (int q = 0; q < 8; q++) {
            int u = tid + q*256;
            int m = u >> 4, c16 = u & 15;
            int h = m >> 6, j = m & 63;
            int y = iy0 + h + kyi;
            int col = xb + j;
            bool ok = (y >= 0 && y < HIN && col >= 0 && col < WIN);
            int yc = ok ? y : 0; int cc = ok ? col : 0;
            const float* gsrc = src + ((size_t)((n*HIN + yc)*WIN + cc))*CI + ci0 + 4*c16;
            cp16z(&A[m*68 + 4*c16], gsrc, ok ? 16u : 0u);
        }
        int k0 = ((kyA + 2*kyi)*4 + (t + 2*kxi))*CI + ci0;
#pragma unroll
        for (int q = 0; q < 8; q++) {
            int u = tid + q*256;
            int kk = u >> 5, c32 = u & 31;
            cp16z(&B[kk*132 + 4*c32], &wt[(size_t)(k0 + kk)*128 + 4*c32], 16u);
        }
        CPA_COMMIT();
    };

    stage(0, 0);
#pragma unroll 1
    for (int c = 0; c < NCH; c++) {
        if (c + 1 < NCH) {
            stage(c + 1, (c + 1) & 1);
            asm volatile("cp.async.wait_group 1;");
        } else {
            asm volatile("cp.async.wait_group 0;");
        }
        __syncthreads();
        const float* As = smf + (c & 1) * 8704;
        const float* Bs = smf + 17408 + (c & 1) * 8448;
#pragma unroll
        for (int ks = 0; ks < 8; ks++) {
            int kk = ks * 8;
            wmma::fragment<wmma::matrix_a, 16, 16, 8, wmma::precision::tf32, wmma::row_major> af[2];
#pragma unroll
            for (int im = 0; im < 2; im++)
                wmma::load_matrix_sync(af[im], &As[(m0 + 16*im)*68 + kk], 68);
#pragma unroll
            for (int in = 0; in < 4; in++) {
                wmma::fragment<wmma::matrix_b, 16, 16, 8, wmma::precision::tf32, wmma::row_major> bf;
                wmma::load_matrix_sync(bf, &Bs[kk*132 + n0 + 16*in], 132);
#pragma unroll
                for (int im = 0; im < 2; im++)
                    wmma::mma_sync(acc[im][in], af[im], bf, acc[im][in]);
            }
        }
        __syncthreads();
    }
#pragma unroll
    for (int im = 0; im < 2; im++)
#pragma unroll
        for (int in = 0; in < 4; in++)
            wmma::store_matrix_sync(&Cs[(m0 + 16*im)*132 + n0 + 16*in],
                                    acc[im][in], 132, wmma::mem_row_major);
    __syncthreads();
    // epilogue
    {
        int m = tid >> 1;
        int half = tid & 1;
        int h = m >> 6, j = m & 63;
        int row = oy + 2*h;
        int ox = x0 + 2*j + t;
        const float* cp = &Cs[m*132 + half*64];
        if (RGB) {
            float r = 0.0f, g = 0.0f, bl = 0.0f;
#pragma unroll 8
            for (int kk = 0; kk < 64; kk++) {
                int cc = half*64 + kk;
                float gv = gelu_f(cp[kk] + biass[cc]);
                r  = fmaf(gv, w3s[cc*3+0], r);
                g  = fmaf(gv, w3s[cc*3+1], g);
                bl = fmaf(gv, w3s[cc*3+2], bl);
            }
            r  += __shfl_xor_sync(0xffffffffu, r, 1);
            g  += __shfl_xor_sync(0xffffffffu, g, 1);
            bl += __shfl_xor_sync(0xffffffffu, bl, 1);
            if (half == 0) {
                float* dp = dst + ((size_t)((n*HOUT + row)*WOUT + ox))*3;
                dp[0] = r + b3s[0];
                dp[1] = g + b3s[1];
                dp[2] = bl + b3s[2];
            }
        } else {
            // pre-round to tf32 so convt2's cp.async staging needs no conversion
            float* dp = dst + ((size_t)((n*HOUT + row)*WOUT + ox))*128 + half*64;
#pragma unroll
            for (int k4 = 0; k4 < 16; k4++) {
                float4 o;
                o.x = tf32r(gelu_f(cp[4*k4+0] + biass[half*64 + 4*k4+0]));
                o.y = tf32r(gelu_f(cp[4*k4+1] + biass[half*64 + 4*k4+1]));
                o.z = tf32r(gelu_f(cp[4*k4+2] + biass[half*64 + 4*k4+2]));
                o.w = tf32r(gelu_f(cp[4*k4+3] + biass[half*64 + 4*k4+3]));
                *reinterpret_cast<float4*>(dp + 4*k4) = o;
            }
        }
    }
}

// ================= finalize losses =================
__global__ void k_final(float* __restrict__ dout) {
    float l = g_loss / (float)(TOK_ELEMS * EMB);
    dout[LOSS_OFF]     = l;
    dout[LOSS_OFF + 1] = l;
}

// ================= launch =================
extern "C" void kernel_launch(void* const* d_in, const int* in_sizes, int n_in,
                              void* d_out, int out_size) {
    const float* x      = (const float*)d_in[0];
    const float* enc_w1 = (const float*)d_in[1];
    const float* enc_b1 = (const float*)d_in[2];
    const float* enc_w2 = (const float*)d_in[3];
    const float* enc_b2 = (const float*)d_in[4];
    const float* enc_w3 = (const float*)d_in[5];
    const float* enc_b3 = (const float*)d_in[6];
    const float* cb     = (const float*)d_in[7];
    const float* dec_w1 = (const float*)d_in[8];
    const float* dec_b1 = (const float*)d_in[9];
    const float* dec_w2 = (const float*)d_in[10];
    const float* dec_b2 = (const float*)d_in[11];
    const float* dec_w3 = (const float*)d_in[12];
    const float* dec_b3 = (const float*)d_in[13];
    float* out = (float*)d_out;

    float* wt1p; cudaGetSymbolAddress((void**)&wt1p, g_wt1);
    float* wt2p; cudaGetSymbolAddress((void**)&wt2p, g_wt2);
    float* zstp; cudaGetSymbolAddress((void**)&zstp, g_zst);
    float* g1p;  cudaGetSymbolAddress((void**)&g1p, g_g1);

    const int smem_dec = 34820 * 4;   // 139280 B
    static int smem_set = 0;
    if (!smem_set) {
        cudaFuncSetAttribute(k_convt_wmma<64, 64, 64, false>,
                             cudaFuncAttributeMaxDynamicSharedMemorySize, smem_dec);
        cudaFuncSetAttribute(k_convt_wmma<128, 128, 128, true>,
                             cudaFuncAttributeMaxDynamicSharedMemorySize, smem_dec);
        smem_set = 1;
    }

    k_prep_tf32<<<512, 256>>>(dec_w1, wt1p, 131072);
    k_prep_tf32<<<1024, 256>>>(dec_w2, wt2p, 262144);

    k_conv1<<<dim3(8, 128, 16), 128>>>(x, enc_w1, enc_b1);
    k_conv2<<<dim3(64, 16), 128>>>(enc_w2, enc_b2, enc_w3, enc_b3);
    k_vq<<<4096, 128>>>(cb, out);

    k_convt_wmma<64, 64, 64, false><<<dim3(2, 64, 16), 256, smem_dec>>>(
        zstp, wt1p, dec_b1, nullptr, nullptr, g1p);
    k_convt_wmma<128, 128, 128, true><<<dim3(4, 128, 16), 256, smem_dec>>>(
        g1p, wt2p, dec_b2, dec_w3, dec_b3, out);
    k_final<<<1, 1>>>(out);
}

// round 13
// speedup vs baseline: 2.7323x; 2.7323x over previous
#include <cuda_runtime.h>
#include <cuda_fp16.h>
#include <math.h>
#include <mma.h>

using namespace nvcuda;

// ---------------- sizes ----------------
#define BATCH 16
#define H0 256
#define W0 256
#define CIN 3
#define HID 128
#define EMB 64
#define KCODES 1024
#define H1v 128
#define W1v 128
#define H2v 64
#define W2v 64

#define XREC_ELEMS (BATCH*H0*W0*3)      // 3145728
#define TOK_OFF    XREC_ELEMS
#define TOK_ELEMS  (BATCH*H2v*W2v)      // 65536
#define LOSS_OFF   (TOK_OFF + TOK_ELEMS)

typedef unsigned long long u64;
typedef unsigned int u32;

// ---------------- scratch ----------------
__device__ float  g_h1[BATCH*H1v*W1v*HID];    // encoder conv1 out (gelu'd)
__device__ float  g_ze[BATCH*H2v*W2v*EMB];    // z_e (fp32)
__device__ __half g_zsth[BATCH*H2v*W2v*EMB];  // z_st (half, for decoder MMA)
__device__ __half g_g1h[BATCH*H1v*W1v*HID];   // decoder convt1 out (half)
__device__ __half g_wt1h[1024*128];           // dec_w1 half
__device__ __half g_wt2h[2048*128];           // dec_w2 half
__device__ float  g_loss;

__device__ __forceinline__ float gelu_f(float x) {
    float t = 0.7978845608028654f * (x + 0.044715f * x * x * x);
    return 0.5f * x * (1.0f + tanhf(t));
}

// ---------------- packed f32x2 helpers ----------------
__device__ __forceinline__ u64 splat2(float a) {
    u64 r; asm("mov.b64 %0, {%1, %1};" : "=l"(r) : "f"(a)); return r;
}
__device__ __forceinline__ u64 pack2(float lo, float hi) {
    u64 r; asm("mov.b64 %0, {%1, %2};" : "=l"(r) : "f"(lo), "f"(hi)); return r;
}
__device__ __forceinline__ void unpack2(u64 v, float& lo, float& hi) {
    asm("mov.b64 {%0, %1}, %2;" : "=f"(lo), "=f"(hi) : "l"(v));
}
__device__ __forceinline__ void ffma2(u64& d, u64 a, u64 b) {
    asm("fma.rn.f32x2 %0, %1, %2, %0;" : "+l"(d) : "l"(a), "l"(b));
}
#define FFMA2_8(J, AJ) { u64 s_ = splat2(AJ); \
    ffma2(acc2[J][0], s_, w01); ffma2(acc2[J][1], s_, w23); \
    ffma2(acc2[J][2], s_, w45); ffma2(acc2[J][3], s_, w67); }

// ================= prep: fp16 convert =================
__global__ void k_prep_half(const float* __restrict__ w, __half* __restrict__ o, int n) {
    int i = blockIdx.x * 256 + threadIdx.x;
    if (i < n) o[i] = __float2half(w[i]);
}

// ================= conv1: x -> h1, 4x4 s2 SAME, gelu (fp32) =================
__global__ void k_conv1(const float* __restrict__ x, const float* __restrict__ w,
                        const float* __restrict__ b) {
    __shared__ float ws[4*4*3*128];
    __shared__ float ins[4*34*3];
    int tid = threadIdx.x;
    int bx = blockIdx.x, oy = blockIdx.y, n = blockIdx.z;
    if (bx == 0 && oy == 0 && n == 0 && tid == 0) g_loss = 0.0f;
    for (int i = tid; i < 6144; i += 128) ws[i] = w[i];
    int x0 = bx * 16;
    for (int i = tid; i < 4*34*3; i += 128) {
        int r = i / (34*3); int rem = i - r*(34*3); int c = rem / 3; int ch = rem % 3;
        int gy = 2*oy - 1 + r;
        int gx = 2*x0 - 1 + c;
        float v = 0.0f;
        if (gy >= 0 && gy < H0 && gx >= 0 && gx < W0) v = x[((n*H0+gy)*W0+gx)*CIN + ch];
        ins[i] = v;
    }
    __syncthreads();
    int co = tid;
    float bias = b[co];
    u64 acc2[8];
#pragma unroll
    for (int pp = 0; pp < 8; pp++) acc2[pp] = pack2(bias, bias);
    for (int ky = 0; ky < 4; ky++) {
        for (int kx = 0; kx < 4; kx++) {
#pragma unroll
            for (int ci = 0; ci < 3; ci++) {
                float wv = ws[((ky*4+kx)*3+ci)*128 + co];
                u64 wvv = splat2(wv);
#pragma unroll
                for (int pp = 0; pp < 8; pp++) {
                    u64 av = pack2(ins[(ky*34 + 4*pp + kx)*3 + ci],
                                   ins[(ky*34 + 4*pp + 2 + kx)*3 + ci]);
                    ffma2(acc2[pp], av, wvv);
                }
            }
        }
    }
#pragma unroll
    for (int pp = 0; pp < 8; pp++) {
        float v0, v1; unpack2(acc2[pp], v0, v1);
        g_h1[((n*H1v+oy)*W1v + x0 + 2*pp)*HID + co]     = gelu_f(v0);
        g_h1[((n*H1v+oy)*W1v + x0 + 2*pp + 1)*HID + co] = gelu_f(v1);
    }
}

// ================= conv2 (GEMM-tiled, f32x2) + gelu + 1x1: h1 -> z_e =================
__global__ void __launch_bounds__(128) k_conv2(const float* __restrict__ w2, const float* __restrict__ b2,
                                               const float* __restrict__ w3, const float* __restrict__ b3) {
    __shared__ float sm[2112 + 8192];
    float* ins = sm;
    float* Bs  = sm + 2112;
    float* h2s = sm;
    int tid = threadIdx.x;
    int oy = blockIdx.x, n = blockIdx.y;
    int pa = tid & 7, cg = tid >> 3;
    int co0 = cg * 8;
    u64 acc2[8][4];
    {
        float4 b0 = *reinterpret_cast<const float4*>(&b2[co0]);
        float4 b1 = *reinterpret_cast<const float4*>(&b2[co0+4]);
        u64 p0 = pack2(b0.x,b0.y), p1 = pack2(b0.z,b0.w);
        u64 p2 = pack2(b1.x,b1.y), p3 = pack2(b1.z,b1.w);
#pragma unroll
        for (int j = 0; j < 8; j++) { acc2[j][0]=p0; acc2[j][1]=p1; acc2[j][2]=p2; acc2[j][3]=p3; }
    }
    int axbase = 2 * pa;
#pragma unroll 1
    for (int ch = 0; ch < 32; ch++) {
        int ci0 = ch * 4;
        for (int i = tid; i < 520; i += 128) {
            int r = i / 130; int ixl = i - r*130;
            int iy = 2*oy - 1 + r;
            int ix = ixl - 1;
            float4 v = make_float4(0,0,0,0);
            if (iy >= 0 && iy < H1v && ix >= 0 && ix < W1v)
                v = *reinterpret_cast<const float4*>(&g_h1[((n*H1v+iy)*W1v+ix)*HID + ci0]);
            float* dst = &ins[(r*4)*132 + ixl];
            dst[0] = v.x; dst[132] = v.y; dst[264] = v.z; dst[396] = v.w;
        }
        for (int i = tid; i < 2048; i += 128) {
            int co4 = i & 31; int cik = (i >> 5) & 3; int tap = i >> 7;
            float4 wv = *reinterpret_cast<const float4*>(&w2[((tap*HID) + ci0 + cik)*HID + co4*4]);
            *reinterpret_cast<float4*>(&Bs[(tap*4+cik)*128 + co4*4]) = wv;
        }
        __syncthreads();
        for (int tap = 0; tap < 16; tap++) {
            int kx = tap & 3; int row = tap >> 2;
#pragma unroll
            for (int cik = 0; cik < 4; cik++) {
                const u64* bp = reinterpret_cast<const u64*>(&Bs[(tap*4+cik)*128 + co0]);
                u64 w01 = bp[0], w23 = bp[1], w45 = bp[2], w67 = bp[3];
                const float* ap = &ins[(row*4+cik)*132 + axbase + kx];
                float a0 = ap[0],  a1 = ap[16], a2 = ap[32], a3 = ap[48];
                float a4 = ap[64], a5 = ap[80], a6 = ap[96], a7 = ap[112];
                FFMA2_8(0,a0) FFMA2_8(1,a1) FFMA2_8(2,a2) FFMA2_8(3,a3)
                FFMA2_8(4,a4) FFMA2_8(5,a5) FFMA2_8(6,a6) FFMA2_8(7,a7)
            }
        }
        __syncthreads();
    }
#pragma unroll
    for (int j = 0; j < 8; j++) {
        int ox = pa + 8*j;
        float f0,f1,f2,f3,f4,f5,f6,f7;
        unpack2(acc2[j][0], f0, f1); unpack2(acc2[j][1], f2, f3);
        unpack2(acc2[j][2], f4, f5); unpack2(acc2[j][3], f6, f7);
        float4 o0 = make_float4(gelu_f(f0), gelu_f(f1), gelu_f(f2), gelu_f(f3));
        float4 o1 = make_float4(gelu_f(f4), gelu_f(f5), gelu_f(f6), gelu_f(f7));
        *reinterpret_cast<float4*>(&h2s[ox*132 + co0])     = o0;
        *reinterpret_cast<float4*>(&h2s[ox*132 + co0 + 4]) = o1;
    }
    __syncthreads();
    {
        int px = tid >> 1;
        int e0 = (tid & 1) * 32;
        u64 z2[16];
#pragma unroll
        for (int u = 0; u < 8; u++) {
            float4 bb = *reinterpret_cast<const float4*>(&b3[e0 + 4*u]);
            z2[2*u]   = pack2(bb.x, bb.y);
            z2[2*u+1] = pack2(bb.z, bb.w);
        }
#pragma unroll 4
        for (int ci = 0; ci < 128; ci++) {
            float hv = h2s[px*132 + ci];
            u64 s = splat2(hv);
#pragma unroll
            for (int u = 0; u < 8; u++) {
                float4 wv = *reinterpret_cast<const float4*>(&w3[ci*EMB + e0 + 4*u]);
                ffma2(z2[2*u],   s, pack2(wv.x, wv.y));
                ffma2(z2[2*u+1], s, pack2(wv.z, wv.w));
            }
        }
        float* dst = &g_ze[((n*H2v+oy)*W2v + px)*EMB + e0];
#pragma unroll
        for (int u = 0; u < 8; u++) {
            float f0,f1,f2,f3;
            unpack2(z2[2*u], f0, f1); unpack2(z2[2*u+1], f2, f3);
            *reinterpret_cast<float4*>(dst + 4*u) = make_float4(f0, f1, f2, f3);
        }
    }
}

// ================= VQ (fp32; writes z_st as half for decoder) =================
#define CSTR 68
__global__ void k_vq(const float* __restrict__ cb, float* __restrict__ dout) {
    __shared__ float cs[64*CSTR];
    __shared__ float e2s[64];
    __shared__ float bval[128];
    __shared__ int   bidx[128];
    __shared__ int   widx[16];
    __shared__ float lred[128];
    int tid = threadIdx.x;
    int pb = blockIdx.x * 16;
    int p = tid & 15;
    int g = tid >> 4;
    float4 z4[16];
    const float* zp = &g_ze[(pb + p)*EMB];
#pragma unroll
    for (int i = 0; i < 16; i++) z4[i] = *reinterpret_cast<const float4*>(&zp[4*i]);
    float best = 3.4e38f; int bi = 0;
    for (int ch = 0; ch < 16; ch++) {
        for (int i = tid; i < 64*16; i += 128) {
            int cj = i >> 4; int d4 = i & 15;
            float4 v = *reinterpret_cast<const float4*>(&cb[(ch*64+cj)*EMB + 4*d4]);
            *reinterpret_cast<float4*>(&cs[cj*CSTR + 4*d4]) = v;
        }
        __syncthreads();
        if (tid < 64) {
            float s = 0.0f;
#pragma unroll 8
            for (int d = 0; d < 64; d++) { float c = cs[tid*CSTR + d]; s = fmaf(c, c, s); }
            e2s[tid] = s;
        }
        __syncthreads();
#pragma unroll
        for (int j = 0; j < 8; j++) {
            int cj = g*8 + j;
            const float* cp = &cs[cj*CSTR];
            float dot = 0.0f;
#pragma unroll
            for (int i = 0; i < 16; i++) {
                float4 c = *reinterpret_cast<const float4*>(&cp[4*i]);
                dot = fmaf(z4[i].x, c.x, dot); dot = fmaf(z4[i].y, c.y, dot);
                dot = fmaf(z4[i].z, c.z, dot); dot = fmaf(z4[i].w, c.w, dot);
            }
            float dist = e2s[cj] - 2.0f*dot;
            int gidx = ch*64 + cj;
            if (dist < best || (dist == best && gidx < bi)) { best = dist; bi = gidx; }
        }
        __syncthreads();
    }
    bval[tid] = best; bidx[tid] = bi;
    __syncthreads();
    if (tid < 16) {
        float bb = bval[tid]; int bbi = bidx[tid];
        for (int k = 1; k < 8; k++) {
            float v = bval[tid + 16*k]; int vi = bidx[tid + 16*k];
            if (v < bb || (v == bb && vi < bbi)) { bb = v; bbi = vi; }
        }
        widx[tid] = bbi;
        dout[TOK_OFF + pb + tid] = (float)bbi;
    }
    __syncthreads();
    int idx = widx[p];
    float lsum = 0.0f;
    const float* cq = &cb[idx*EMB + g*8];
    const float* ze = &g_ze[(pb + p)*EMB + g*8];
    __half*      zs = &g_zsth[(pb + p)*EMB + g*8];
#pragma unroll
    for (int d = 0; d < 8; d++) {
        float zq = cq[d]; float z = ze[d];
        float diff = zq - z;
        zs[d] = __float2half(z + diff);
        lsum = fmaf(diff, diff, lsum);
    }
    lred[tid] = lsum;
    __syncthreads();
    for (int s = 64; s > 0; s >>= 1) {
        if (tid < s) lred[tid] += lred[tid + s];
        __syncthreads();
    }
    if (tid == 0) atomicAdd(&g_loss, lred[0]);
}

// ================= WMMA fp16 transposed-conv =================
// CTA: one parity tile. M=128 (2 out rows x 64 same-parity px), N=128 co,
// K = 2kyi*2kxi*CI in chunks of 64. 256 threads = 8 warps (4m x 2n). occ 2.
// smem: As half[128][72] | Bs half[64][136]; Cs float[128][132] reuse; bias after.
template<int CI, int HIN, int WIN, bool RGB>
__global__ void __launch_bounds__(256, 2) k_convt_wmma(
    const __half* __restrict__ src, const __half* __restrict__ wt,
    const float* __restrict__ bias,
    const float* __restrict__ w3, const float* __restrict__ b3,
    void* __restrict__ dstv)
{
    constexpr int CIC64 = CI / 64;
    constexpr int NCH   = 4 * CIC64;
    constexpr int HOUT  = 2 * HIN;
    constexpr int WOUT  = 2 * WIN;

    extern __shared__ float smf[];
    __half* As   = reinterpret_cast<__half*>(smf);          // [128][72] halves
    __half* Bs   = reinterpret_cast<__half*>(smf + 4608);   // [64][136] halves
    float* Cs    = smf;             // epilogue reuse: 128*132 floats
    float* biass = smf + 17152;     // 128
    float* w3s   = smf + 17280;     // 384
    float* b3s   = smf + 17664;     // 3

    int tid = threadIdx.x;
    int bx = blockIdx.x, pr = blockIdx.y, n = blockIdx.z;
    int t  = bx & 1;
    int xh = bx >> 1;
    int oy = 4*(pr >> 1) + (pr & 1);          // rows oy, oy+2
    int x0 = xh * 128;
    int xhalf = x0 >> 1;
    int kyA = oy & 1;
    int iy0 = (oy + kyA - 2) >> 1;

    for (int i = tid; i < 128; i += 256) biass[i] = bias[i];
    if (RGB) {
        for (int i = tid; i < 384; i += 256) w3s[i] = w3[i];
        if (tid < 3) b3s[tid] = b3[tid];
    }

    int wid = tid >> 5;
    int m0 = (wid & 3) * 32;
    int n0 = (wid >> 2) * 64;

    wmma::fragment<wmma::accumulator, 16, 16, 16, float> acc[2][4];
#pragma unroll
    for (int im = 0; im < 2; im++)
#pragma unroll
        for (int in = 0; in < 4; in++) wmma::fill_fragment(acc[im][in], 0.0f);

#pragma unroll 1
    for (int c = 0; c < NCH; c++) {
        int kyi = c / (2*CIC64);
        int kxi = (c / CIC64) & 1;
        int ci0 = (c % CIC64) * 64;
        __syncthreads();
        // stage A: 128 rows x 64 halves = 1024 uint4 (8 halves each)
        {
            int xb = xhalf + t + kxi - 1;
#pragma unroll
            for (int q = 0; q < 4; q++) {
                int u = tid + q*256;
                int m = u >> 3, c8 = u & 7;
                int h = m >> 6, j = m & 63;
                int y = iy0 + h + kyi;
                int col = xb + j;
                uint4 v = make_uint4(0,0,0,0);
                if (y >= 0 && y < HIN && col >= 0 && col < WIN)
                    v = *reinterpret_cast<const uint4*>(
                        &src[((size_t)((n*HIN + y)*WIN + col))*CI + ci0 + 8*c8]);
                *reinterpret_cast<uint4*>(&As[m*72 + 8*c8]) = v;
            }
        }
        // stage B: 64 k-rows x 128 co halves = 1024 uint4 (16 per row)
        {
            int k0 = ((kyA + 2*kyi)*4 + (t + 2*kxi))*CI + ci0;
#pragma unroll
            for (int q = 0; q < 4; q++) {
                int u = tid + q*256;
                int kk = u >> 4, c16 = u & 15;
                uint4 v = *reinterpret_cast<const uint4*>(&wt[(size_t)(k0 + kk)*128 + 8*c16]);
                *reinterpret_cast<uint4*>(&Bs[kk*136 + 8*c16]) = v;
            }
        }
        __syncthreads();
#pragma unroll
        for (int ks = 0; ks < 4; ks++) {
            int kk = ks * 16;
            wmma::fragment<wmma::matrix_a, 16, 16, 16, __half, wmma::row_major> af[2];
#pragma unroll
            for (int im = 0; im < 2; im++)
                wmma::load_matrix_sync(af[im], &As[(m0 + 16*im)*72 + kk], 72);
#pragma unroll
            for (int in = 0; in < 4; in++) {
                wmma::fragment<wmma::matrix_b, 16, 16, 16, __half, wmma::row_major> bf;
                wmma::load_matrix_sync(bf, &Bs[kk*136 + n0 + 16*in], 136);
#pragma unroll
                for (int im = 0; im < 2; im++)
                    wmma::mma_sync(acc[im][in], af[im], bf, acc[im][in]);
            }
        }
    }
    __syncthreads();
#pragma unroll
    for (int im = 0; im < 2; im++)
#pragma unroll
        for (int in = 0; in < 4; in++)
            wmma::store_matrix_sync(&Cs[(m0 + 16*im)*132 + n0 + 16*in],
                                    acc[im][in], 132, wmma::mem_row_major);
    __syncthreads();
    // epilogue
    {
        int m = tid >> 1;
        int half = tid & 1;
        int h = m >> 6, j = m & 63;
        int row = oy + 2*h;
        int ox = x0 + 2*j + t;
        const float* cp = &Cs[m*132 + half*64];
        if (RGB) {
            float* dst = reinterpret_cast<float*>(dstv);
            float r = 0.0f, g = 0.0f, bl = 0.0f;
#pragma unroll 8
            for (int kk = 0; kk < 64; kk++) {
                int cc = half*64 + kk;
                float gv = gelu_f(cp[kk] + biass[cc]);
                r  = fmaf(gv, w3s[cc*3+0], r);
                g  = fmaf(gv, w3s[cc*3+1], g);
                bl = fmaf(gv, w3s[cc*3+2], bl);
            }
            r  += __shfl_xor_sync(0xffffffffu, r, 1);
            g  += __shfl_xor_sync(0xffffffffu, g, 1);
            bl += __shfl_xor_sync(0xffffffffu, bl, 1);
            if (half == 0) {
                float* dp = dst + ((size_t)((n*HOUT + row)*WOUT + ox))*3;
                dp[0] = r + b3s[0];
                dp[1] = g + b3s[1];
                dp[2] = bl + b3s[2];
            }
        } else {
            __half* dst = reinterpret_cast<__half*>(dstv);
            __half* dp = dst + ((size_t)((n*HOUT + row)*WOUT + ox))*128 + half*64;
#pragma unroll
            for (int k2 = 0; k2 < 32; k2++) {
                float a = gelu_f(cp[2*k2+0] + biass[half*64 + 2*k2+0]);
                float b = gelu_f(cp[2*k2+1] + biass[half*64 + 2*k2+1]);
                *reinterpret_cast<__half2*>(dp + 2*k2) = __floats2half2_rn(a, b);
            }
        }
    }
}

// ================= finalize losses =================
__global__ void k_final(float* __restrict__ dout) {
    float l = g_loss / (float)(TOK_ELEMS * EMB);
    dout[LOSS_OFF]     = l;
    dout[LOSS_OFF + 1] = l;
}

// ================= launch =================
extern "C" void kernel_launch(void* const* d_in, const int* in_sizes, int n_in,
                              void* d_out, int out_size) {
    const float* x      = (const float*)d_in[0];
    const float* enc_w1 = (const float*)d_in[1];
    const float* enc_b1 = (const float*)d_in[2];
    const float* enc_w2 = (const float*)d_in[3];
    const float* enc_b2 = (const float*)d_in[4];
    const float* enc_w3 = (const float*)d_in[5];
    const float* enc_b3 = (const float*)d_in[6];
    const float* cb     = (const float*)d_in[7];
    const float* dec_w1 = (const float*)d_in[8];
    const float* dec_b1 = (const float*)d_in[9];
    const float* dec_w2 = (const float*)d_in[10];
    const float* dec_b2 = (const float*)d_in[11];
    const float* dec_w3 = (const float*)d_in[12];
    const float* dec_b3 = (const float*)d_in[13];
    float* out = (float*)d_out;

    __half* wt1p; cudaGetSymbolAddress((void**)&wt1p, g_wt1h);
    __half* wt2p; cudaGetSymbolAddress((void**)&wt2p, g_wt2h);
    __half* zstp; cudaGetSymbolAddress((void**)&zstp, g_zsth);
    __half* g1p;  cudaGetSymbolAddress((void**)&g1p, g_g1h);

    const int smem_dec = 17667 * 4;   // 70668 B (occ 2)
    static int smem_set = 0;
    if (!smem_set) {
        cudaFuncSetAttribute(k_convt_wmma<64, 64, 64, false>,
                             cudaFuncAttributeMaxDynamicSharedMemorySize, smem_dec);
        cudaFuncSetAttribute(k_convt_wmma<128, 128, 128, true>,
                             cudaFuncAttributeMaxDynamicSharedMemorySize, smem_dec);
        smem_set = 1;
    }

    k_prep_half<<<512, 256>>>(dec_w1, wt1p, 131072);
    k_prep_half<<<1024, 256>>>(dec_w2, wt2p, 262144);

    k_conv1<<<dim3(8, 128, 16), 128>>>(x, enc_w1, enc_b1);
    k_conv2<<<dim3(64, 16), 128>>>(enc_w2, enc_b2, enc_w3, enc_b3);
    k_vq<<<4096, 128>>>(cb, out);

    k_convt_wmma<64, 64, 64, false><<<dim3(2, 64, 16), 256, smem_dec>>>(
        zstp, wt1p, dec_b1, nullptr, nullptr, g1p);
    k_convt_wmma<128, 128, 128, true><<<dim3(4, 128, 16), 256, smem_dec>>>(
        g1p, wt2p, dec_b2, dec_w3, dec_b3, out);
    k_final<<<1, 1>>>(out);
}

// round 14
// speedup vs baseline: 3.3644x; 1.2313x over previous
#include <cuda_runtime.h>
#include <cuda_fp16.h>
#include <math.h>
#include <mma.h>

using namespace nvcuda;

// ---------------- sizes ----------------
#define BATCH 16
#define H0 256
#define W0 256
#define CIN 3
#define HID 128
#define EMB 64
#define KCODES 1024
#define H1v 128
#define W1v 128
#define H2v 64
#define W2v 64

#define XREC_ELEMS (BATCH*H0*W0*3)      // 3145728
#define TOK_OFF    XREC_ELEMS
#define TOK_ELEMS  (BATCH*H2v*W2v)      // 65536
#define LOSS_OFF   (TOK_OFF + TOK_ELEMS)

typedef unsigned long long u64;
typedef unsigned int u32;

// ---------------- scratch ----------------
__device__ __half g_h1h[BATCH*H1v*W1v*HID];   // conv1 out (gelu'd), fp16 high
__device__ __half g_h1l[BATCH*H1v*W1v*HID];   // fp16 low (residual)
__device__ float  g_ze[BATCH*H2v*W2v*EMB];    // z_e (fp32)
__device__ __half g_zsth[BATCH*H2v*W2v*EMB];  // z_st (half, for decoder MMA)
__device__ __half g_g1h[BATCH*H1v*W1v*HID];   // decoder convt1 out (half)
__device__ __half g_wt1h[1024*128];           // dec_w1 half
__device__ __half g_wt2h[2048*128];           // dec_w2 half
__device__ __half g_w2hh[2048*128];           // enc_w2 half high
__device__ __half g_w2ll[2048*128];           // enc_w2 half low
__device__ float  g_loss;

__device__ __forceinline__ float gelu_f(float x) {
    float t = 0.7978845608028654f * (x + 0.044715f * x * x * x);
    return 0.5f * x * (1.0f + tanhf(t));
}

// ---------------- packed f32x2 helpers ----------------
__device__ __forceinline__ u64 splat2(float a) {
    u64 r; asm("mov.b64 %0, {%1, %1};" : "=l"(r) : "f"(a)); return r;
}
__device__ __forceinline__ u64 pack2(float lo, float hi) {
    u64 r; asm("mov.b64 %0, {%1, %2};" : "=l"(r) : "f"(lo), "f"(hi)); return r;
}
__device__ __forceinline__ void unpack2(u64 v, float& lo, float& hi) {
    asm("mov.b64 {%0, %1}, %2;" : "=f"(lo), "=f"(hi) : "l"(v));
}
__device__ __forceinline__ void ffma2(u64& d, u64 a, u64 b) {
    asm("fma.rn.f32x2 %0, %1, %2, %0;" : "+l"(d) : "l"(a), "l"(b));
}

// ================= prep kernels =================
__global__ void k_prep_half(const float* __restrict__ w, __half* __restrict__ o, int n) {
    int i = blockIdx.x * 256 + threadIdx.x;
    if (i < n) o[i] = __float2half(w[i]);
}
__global__ void k_prep_half_split(const float* __restrict__ w, __half* __restrict__ oh,
                                  __half* __restrict__ ol, int n) {
    int i = blockIdx.x * 256 + threadIdx.x;
    if (i < n) {
        float a = w[i];
        __half h = __float2half(a);
        oh[i] = h;
        ol[i] = __float2half(a - __half2float(h));
    }
}

// ================= conv1: x -> h1 (split fp16), 4x4 s2 SAME, gelu =================
__global__ void k_conv1(const float* __restrict__ x, const float* __restrict__ w,
                        const float* __restrict__ b) {
    __shared__ float ws[4*4*3*128];
    __shared__ float ins[4*34*3];
    int tid = threadIdx.x;
    int bx = blockIdx.x, oy = blockIdx.y, n = blockIdx.z;
    if (bx == 0 && oy == 0 && n == 0 && tid == 0) g_loss = 0.0f;
    for (int i = tid; i < 6144; i += 128) ws[i] = w[i];
    int x0 = bx * 16;
    for (int i = tid; i < 4*34*3; i += 128) {
        int r = i / (34*3); int rem = i - r*(34*3); int c = rem / 3; int ch = rem % 3;
        int gy = 2*oy - 1 + r;
        int gx = 2*x0 - 1 + c;
        float v = 0.0f;
        if (gy >= 0 && gy < H0 && gx >= 0 && gx < W0) v = x[((n*H0+gy)*W0+gx)*CIN + ch];
        ins[i] = v;
    }
    __syncthreads();
    int co = tid;
    float bias = b[co];
    u64 acc2[8];
#pragma unroll
    for (int pp = 0; pp < 8; pp++) acc2[pp] = pack2(bias, bias);
    for (int ky = 0; ky < 4; ky++) {
        for (int kx = 0; kx < 4; kx++) {
#pragma unroll
            for (int ci = 0; ci < 3; ci++) {
                float wv = ws[((ky*4+kx)*3+ci)*128 + co];
                u64 wvv = splat2(wv);
#pragma unroll
                for (int pp = 0; pp < 8; pp++) {
                    u64 av = pack2(ins[(ky*34 + 4*pp + kx)*3 + ci],
                                   ins[(ky*34 + 4*pp + 2 + kx)*3 + ci]);
                    ffma2(acc2[pp], av, wvv);
                }
            }
        }
    }
#pragma unroll
    for (int pp = 0; pp < 8; pp++) {
        float v0, v1; unpack2(acc2[pp], v0, v1);
        float g0 = gelu_f(v0), g1 = gelu_f(v1);
        size_t i0 = (size_t)((n*H1v+oy)*W1v + x0 + 2*pp)*HID + co;
        size_t i1 = i0 + HID;
        __half h0 = __float2half(g0), h1 = __float2half(g1);
        g_h1h[i0] = h0; g_h1l[i0] = __float2half(g0 - __half2float(h0));
        g_h1h[i1] = h1; g_h1l[i1] = __float2half(g1 - __half2float(h1));
    }
}

// ================= conv2 WMMA fp16 3-product + gelu + 1x1: h1 -> z_e =================
// M=128 (2 out rows x 64 px), N=128 co, K=2048 (16 taps x 128 ci) in 32 chunks of 64.
// grid (32 pr, 16 n), block 256 = 8 warps (4m x 2n). occ 2.
// smem floats: Ah[0,4608) Al[4608,9216) Bh[9216,13568) Bl[13568,17920)
//              bias[17920,18048) b3s[18048,18112). Cs reuse at 0 (16896).
__global__ void __launch_bounds__(256, 2) k_conv2_wmma(
    const float* __restrict__ b2,
    const float* __restrict__ w3, const float* __restrict__ b3)
{
    extern __shared__ float smf[];
    __half* Ah = reinterpret_cast<__half*>(smf);            // [128][72]
    __half* Al = reinterpret_cast<__half*>(smf + 4608);     // [128][72]
    __half* Bh = reinterpret_cast<__half*>(smf + 9216);     // [64][136]
    __half* Bl = reinterpret_cast<__half*>(smf + 13568);    // [64][136]
    float* Cs  = smf;                                       // reuse [128][132]
    float* b2s = smf + 17920;
    float* b3s = smf + 18048;

    int tid = threadIdx.x;
    int pr = blockIdx.x, n = blockIdx.y;
    int oy0 = pr * 2;

    for (int i = tid; i < 128; i += 256) b2s[i] = b2[i];
    if (tid < 64) b3s[tid] = b3[tid];

    int wid = tid >> 5;
    int m0 = (wid & 3) * 32;
    int n0 = (wid >> 2) * 64;

    wmma::fragment<wmma::accumulator, 16, 16, 16, float> acc[2][4];
#pragma unroll
    for (int im = 0; im < 2; im++)
#pragma unroll
        for (int in = 0; in < 4; in++) wmma::fill_fragment(acc[im][in], 0.0f);

#pragma unroll 1
    for (int c = 0; c < 32; c++) {
        int tap = c >> 1;
        int ci0 = (c & 1) * 64;
        int ky = tap >> 2, kx = tap & 3;
        __syncthreads();
        // stage A (h+l): 128 rows x 64 halves = 1024 uint4 each
#pragma unroll
        for (int q = 0; q < 4; q++) {
            int u = tid + q*256;
            int m = u >> 3, c8 = u & 7;
            int h = m >> 6, j = m & 63;
            int iy = 2*(oy0 + h) - 1 + ky;
            int ix = 2*j - 1 + kx;
            uint4 vh = make_uint4(0,0,0,0), vl = make_uint4(0,0,0,0);
            if (iy >= 0 && iy < H1v && ix >= 0 && ix < W1v) {
                size_t go = ((size_t)((n*H1v + iy)*W1v + ix))*HID + ci0 + 8*c8;
                vh = *reinterpret_cast<const uint4*>(&g_h1h[go]);
                vl = *reinterpret_cast<const uint4*>(&g_h1l[go]);
            }
            *reinterpret_cast<uint4*>(&Ah[m*72 + 8*c8]) = vh;
            *reinterpret_cast<uint4*>(&Al[m*72 + 8*c8]) = vl;
        }
        // stage B (h+l): 64 k-rows x 128 co = 1024 uint4 each
#pragma unroll
        for (int q = 0; q < 4; q++) {
            int u = tid + q*256;
            int kk = u >> 4, c16 = u & 15;
            size_t go = ((size_t)(tap*HID + ci0 + kk))*128 + 8*c16;
            *reinterpret_cast<uint4*>(&Bh[kk*136 + 8*c16]) =
                *reinterpret_cast<const uint4*>(&g_w2hh[go]);
            *reinterpret_cast<uint4*>(&Bl[kk*136 + 8*c16]) =
                *reinterpret_cast<const uint4*>(&g_w2ll[go]);
        }
        __syncthreads();
#pragma unroll
        for (int ks = 0; ks < 4; ks++) {
            int kk = ks * 16;
            wmma::fragment<wmma::matrix_a, 16, 16, 16, __half, wmma::row_major> ahf[2], alf[2];
#pragma unroll
            for (int im = 0; im < 2; im++) {
                wmma::load_matrix_sync(ahf[im], &Ah[(m0 + 16*im)*72 + kk], 72);
                wmma::load_matrix_sync(alf[im], &Al[(m0 + 16*im)*72 + kk], 72);
            }
#pragma unroll
            for (int in = 0; in < 4; in++) {
                wmma::fragment<wmma::matrix_b, 16, 16, 16, __half, wmma::row_major> bhf, blf;
                wmma::load_matrix_sync(bhf, &Bh[kk*136 + n0 + 16*in], 136);
                wmma::load_matrix_sync(blf, &Bl[kk*136 + n0 + 16*in], 136);
#pragma unroll
                for (int im = 0; im < 2; im++) {
                    wmma::mma_sync(acc[im][in], alf[im], bhf, acc[im][in]);
                    wmma::mma_sync(acc[im][in], ahf[im], blf, acc[im][in]);
                    wmma::mma_sync(acc[im][in], ahf[im], bhf, acc[im][in]);
                }
            }
        }
    }
    __syncthreads();
#pragma unroll
    for (int im = 0; im < 2; im++)
#pragma unroll
        for (int in = 0; in < 4; in++)
            wmma::store_matrix_sync(&Cs[(m0 + 16*im)*132 + n0 + 16*in],
                                    acc[im][in], 132, wmma::mem_row_major);
    __syncthreads();
    // bias + gelu in place
    for (int i = tid; i < 128*128; i += 256) {
        int px = i >> 7, ci = i & 127;
        Cs[px*132 + ci] = gelu_f(Cs[px*132 + ci] + b2s[ci]);
    }
    __syncthreads();
    // fused 1x1: 128 -> 64
    {
        int px = tid >> 1;
        int e0 = (tid & 1) * 32;
        u64 z2[16];
#pragma unroll
        for (int u = 0; u < 8; u++) {
            z2[2*u]   = pack2(b3s[e0 + 4*u],     b3s[e0 + 4*u + 1]);
            z2[2*u+1] = pack2(b3s[e0 + 4*u + 2], b3s[e0 + 4*u + 3]);
        }
#pragma unroll 4
        for (int ci = 0; ci < 128; ci++) {
            float hv = Cs[px*132 + ci];
            u64 s = splat2(hv);
#pragma unroll
            for (int u = 0; u < 8; u++) {
                float4 wv = *reinterpret_cast<const float4*>(&w3[ci*EMB + e0 + 4*u]);
                ffma2(z2[2*u],   s, pack2(wv.x, wv.y));
                ffma2(z2[2*u+1], s, pack2(wv.z, wv.w));
            }
        }
        int row = oy0 + (px >> 6), col = px & 63;
        float* dst = &g_ze[((size_t)((n*H2v + row)*W2v + col))*EMB + e0];
#pragma unroll
        for (int u = 0; u < 8; u++) {
            float f0,f1,f2,f3;
            unpack2(z2[2*u], f0, f1); unpack2(z2[2*u+1], f2, f3);
            *reinterpret_cast<float4*>(dst + 4*u) = make_float4(f0, f1, f2, f3);
        }
    }
}

// ================= VQ (fp32; writes z_st as half for decoder) =================
#define CSTR 68
__global__ void k_vq(const float* __restrict__ cb, float* __restrict__ dout) {
    __shared__ float cs[64*CSTR];
    __shared__ float e2s[64];
    __shared__ float bval[128];
    __shared__ int   bidx[128];
    __shared__ int   widx[16];
    __shared__ float lred[128];
    int tid = threadIdx.x;
    int pb = blockIdx.x * 16;
    int p = tid & 15;
    int g = tid >> 4;
    float4 z4[16];
    const float* zp = &g_ze[(pb + p)*EMB];
#pragma unroll
    for (int i = 0; i < 16; i++) z4[i] = *reinterpret_cast<const float4*>(&zp[4*i]);
    float best = 3.4e38f; int bi = 0;
    for (int ch = 0; ch < 16; ch++) {
        for (int i = tid; i < 64*16; i += 128) {
            int cj = i >> 4; int d4 = i & 15;
            float4 v = *reinterpret_cast<const float4*>(&cb[(ch*64+cj)*EMB + 4*d4]);
            *reinterpret_cast<float4*>(&cs[cj*CSTR + 4*d4]) = v;
        }
        __syncthreads();
        if (tid < 64) {
            float s = 0.0f;
#pragma unroll 8
            for (int d = 0; d < 64; d++) { float c = cs[tid*CSTR + d]; s = fmaf(c, c, s); }
            e2s[tid] = s;
        }
        __syncthreads();
#pragma unroll
        for (int j = 0; j < 8; j++) {
            int cj = g*8 + j;
            const float* cp = &cs[cj*CSTR];
            float dot = 0.0f;
#pragma unroll
            for (int i = 0; i < 16; i++) {
                float4 c = *reinterpret_cast<const float4*>(&cp[4*i]);
                dot = fmaf(z4[i].x, c.x, dot); dot = fmaf(z4[i].y, c.y, dot);
                dot = fmaf(z4[i].z, c.z, dot); dot = fmaf(z4[i].w, c.w, dot);
            }
            float dist = e2s[cj] - 2.0f*dot;
            int gidx = ch*64 + cj;
            if (dist < best || (dist == best && gidx < bi)) { best = dist; bi = gidx; }
        }
        __syncthreads();
    }
    bval[tid] = best; bidx[tid] = bi;
    __syncthreads();
    if (tid < 16) {
        float bb = bval[tid]; int bbi = bidx[tid];
        for (int k = 1; k < 8; k++) {
            float v = bval[tid + 16*k]; int vi = bidx[tid + 16*k];
            if (v < bb || (v == bb && vi < bbi)) { bb = v; bbi = vi; }
        }
        widx[tid] = bbi;
        dout[TOK_OFF + pb + tid] = (float)bbi;
    }
    __syncthreads();
    int idx = widx[p];
    float lsum = 0.0f;
    const float* cq = &cb[idx*EMB + g*8];
    const float* ze = &g_ze[(pb + p)*EMB + g*8];
    __half*      zs = &g_zsth[(pb + p)*EMB + g*8];
#pragma unroll
    for (int d = 0; d < 8; d++) {
        float zq = cq[d]; float z = ze[d];
        float diff = zq - z;
        zs[d] = __float2half(z + diff);
        lsum = fmaf(diff, diff, lsum);
    }
    lred[tid] = lsum;
    __syncthreads();
    for (int s = 64; s > 0; s >>= 1) {
        if (tid < s) lred[tid] += lred[tid + s];
        __syncthreads();
    }
    if (tid == 0) atomicAdd(&g_loss, lred[0]);
}

// ================= WMMA fp16 transposed-conv (R13, unchanged) =================
template<int CI, int HIN, int WIN, bool RGB>
__global__ void __launch_bounds__(256, 2) k_convt_wmma(
    const __half* __restrict__ src, const __half* __restrict__ wt,
    const float* __restrict__ bias,
    const float* __restrict__ w3, const float* __restrict__ b3,
    void* __restrict__ dstv)
{
    constexpr int CIC64 = CI / 64;
    constexpr int NCH   = 4 * CIC64;
    constexpr int HOUT  = 2 * HIN;
    constexpr int WOUT  = 2 * WIN;

    extern __shared__ float smf[];
    __half* As   = reinterpret_cast<__half*>(smf);          // [128][72] halves
    __half* Bs   = reinterpret_cast<__half*>(smf + 4608);   // [64][136] halves
    float* Cs    = smf;             // epilogue reuse: 128*132 floats
    float* biass = smf + 17152;     // 128
    float* w3s   = smf + 17280;     // 384
    float* b3s   = smf + 17664;     // 3

    int tid = threadIdx.x;
    int bx = blockIdx.x, pr = blockIdx.y, n = blockIdx.z;
    int t  = bx & 1;
    int xh = bx >> 1;
    int oy = 4*(pr >> 1) + (pr & 1);          // rows oy, oy+2
    int x0 = xh * 128;
    int xhalf = x0 >> 1;
    int kyA = oy & 1;
    int iy0 = (oy + kyA - 2) >> 1;

    for (int i = tid; i < 128; i += 256) biass[i] = bias[i];
    if (RGB) {
        for (int i = tid; i < 384; i += 256) w3s[i] = w3[i];
        if (tid < 3) b3s[tid] = b3[tid];
    }

    int wid = tid >> 5;
    int m0 = (wid & 3) * 32;
    int n0 = (wid >> 2) * 64;

    wmma::fragment<wmma::accumulator, 16, 16, 16, float> acc[2][4];
#pragma unroll
    for (int im = 0; im < 2; im++)
#pragma unroll
        for (int in = 0; in < 4; in++) wmma::fill_fragment(acc[im][in], 0.0f);

#pragma unroll 1
    for (int c = 0; c < NCH; c++) {
        int kyi = c / (2*CIC64);
        int kxi = (c / CIC64) & 1;
        int ci0 = (c % CIC64) * 64;
        __syncthreads();
        // stage A: 128 rows x 64 halves = 1024 uint4
        {
            int xb = xhalf + t + kxi - 1;
#pragma unroll
            for (int q = 0; q < 4; q++) {
                int u = tid + q*256;
                int m = u >> 3, c8 = u & 7;
                int h = m >> 6, j = m & 63;
                int y = iy0 + h + kyi;
                int col = xb + j;
                uint4 v = make_uint4(0,0,0,0);
                if (y >= 0 && y < HIN && col >= 0 && col < WIN)
                    v = *reinterpret_cast<const uint4*>(
                        &src[((size_t)((n*HIN + y)*WIN + col))*CI + ci0 + 8*c8]);
                *reinterpret_cast<uint4*>(&As[m*72 + 8*c8]) = v;
            }
        }
        // stage B: 64 k-rows x 128 co halves = 1024 uint4 (16 per row)
        {
            int k0 = ((kyA + 2*kyi)*4 + (t + 2*kxi))*CI + ci0;
#pragma unroll
            for (int q = 0; q < 4; q++) {
                int u = tid + q*256;
                int kk = u >> 4, c16 = u & 15;
                uint4 v = *reinterpret_cast<const uint4*>(&wt[(size_t)(k0 + kk)*128 + 8*c16]);
                *reinterpret_cast<uint4*>(&Bs[kk*136 + 8*c16]) = v;
            }
        }
        __syncthreads();
#pragma unroll
        for (int ks = 0; ks < 4; ks++) {
            int kk = ks * 16;
            wmma::fragment<wmma::matrix_a, 16, 16, 16, __half, wmma::row_major> af[2];
#pragma unroll
            for (int im = 0; im < 2; im++)
                wmma::load_matrix_sync(af[im], &As[(m0 + 16*im)*72 + kk], 72);
#pragma unroll
            for (int in = 0; in < 4; in++) {
                wmma::fragment<wmma::matrix_b, 16, 16, 16, __half, wmma::row_major> bf;
                wmma::load_matrix_sync(bf, &Bs[kk*136 + n0 + 16*in], 136);
#pragma unroll
                for (int im = 0; im < 2; im++)
                    wmma::mma_sync(acc[im][in], af[im], bf, acc[im][in]);
            }
        }
    }
    __syncthreads();
#pragma unroll
    for (int im = 0; im < 2; im++)
#pragma unroll
        for (int in = 0; in < 4; in++)
            wmma::store_matrix_sync(&Cs[(m0 + 16*im)*132 + n0 + 16*in],
                                    acc[im][in], 132, wmma::mem_row_major);
    __syncthreads();
    // epilogue
    {
        int m = tid >> 1;
        int half = tid & 1;
        int h = m >> 6, j = m & 63;
        int row = oy + 2*h;
        int ox = x0 + 2*j + t;
        const float* cp = &Cs[m*132 + half*64];
        if (RGB) {
            float* dst = reinterpret_cast<float*>(dstv);
            float r = 0.0f, g = 0.0f, bl = 0.0f;
#pragma unroll 8
            for (int kk = 0; kk < 64; kk++) {
                int cc = half*64 + kk;
                float gv = gelu_f(cp[kk] + biass[cc]);
                r  = fmaf(gv, w3s[cc*3+0], r);
                g  = fmaf(gv, w3s[cc*3+1], g);
                bl = fmaf(gv, w3s[cc*3+2], bl);
            }
            r  += __shfl_xor_sync(0xffffffffu, r, 1);
            g  += __shfl_xor_sync(0xffffffffu, g, 1);
            bl += __shfl_xor_sync(0xffffffffu, bl, 1);
            if (half == 0) {
                float* dp = dst + ((size_t)((n*HOUT + row)*WOUT + ox))*3;
                dp[0] = r + b3s[0];
                dp[1] = g + b3s[1];
                dp[2] = bl + b3s[2];
            }
        } else {
            __half* dst = reinterpret_cast<__half*>(dstv);
            __half* dp = dst + ((size_t)((n*HOUT + row)*WOUT + ox))*128 + half*64;
#pragma unroll
            for (int k2 = 0; k2 < 32; k2++) {
                float a = gelu_f(cp[2*k2+0] + biass[half*64 + 2*k2+0]);
                float b = gelu_f(cp[2*k2+1] + biass[half*64 + 2*k2+1]);
                *reinterpret_cast<__half2*>(dp + 2*k2) = __floats2half2_rn(a, b);
            }
        }
    }
}

// ================= finalize losses =================
__global__ void k_final(float* __restrict__ dout) {
    float l = g_loss / (float)(TOK_ELEMS * EMB);
    dout[LOSS_OFF]     = l;
    dout[LOSS_OFF + 1] = l;
}

// ================= launch =================
extern "C" void kernel_launch(void* const* d_in, const int* in_sizes, int n_in,
                              void* d_out, int out_size) {
    const float* x      = (const float*)d_in[0];
    const float* enc_w1 = (const float*)d_in[1];
    const float* enc_b1 = (const float*)d_in[2];
    const float* enc_w2 = (const float*)d_in[3];
    const float* enc_b2 = (const float*)d_in[4];
    const float* enc_w3 = (const float*)d_in[5];
    const float* enc_b3 = (const float*)d_in[6];
    const float* cb     = (const float*)d_in[7];
    const float* dec_w1 = (const float*)d_in[8];
    const float* dec_b1 = (const float*)d_in[9];
    const float* dec_w2 = (const float*)d_in[10];
    const float* dec_b2 = (const float*)d_in[11];
    const float* dec_w3 = (const float*)d_in[12];
    const float* dec_b3 = (const float*)d_in[13];
    float* out = (float*)d_out;

    __half* wt1p; cudaGetSymbolAddress((void**)&wt1p, g_wt1h);
    __half* wt2p; cudaGetSymbolAddress((void**)&wt2p, g_wt2h);
    __half* zstp; cudaGetSymbolAddress((void**)&zstp, g_zsth);
    __half* g1p;  cudaGetSymbolAddress((void**)&g1p, g_g1h);
    __half* w2hp; cudaGetSymbolAddress((void**)&w2hp, g_w2hh);
    __half* w2lp; cudaGetSymbolAddress((void**)&w2lp, g_w2ll);

    const int smem_dec = 17667 * 4;   // 70668 B (occ 2)
    const int smem_c2  = 18112 * 4;   // 72448 B (occ 2)
    static int smem_set = 0;
    if (!smem_set) {
        cudaFuncSetAttribute(k_convt_wmma<64, 64, 64, false>,
                             cudaFuncAttributeMaxDynamicSharedMemorySize, smem_dec);
        cudaFuncSetAttribute(k_convt_wmma<128, 128, 128, true>,
                             cudaFuncAttributeMaxDynamicSharedMemorySize, smem_dec);
        cudaFuncSetAttribute(k_conv2_wmma,
                             cudaFuncAttributeMaxDynamicSharedMemorySize, smem_c2);
        smem_set = 1;
    }

    k_prep_half<<<512, 256>>>(dec_w1, wt1p, 131072);
    k_prep_half<<<1024, 256>>>(dec_w2, wt2p, 262144);
    k_prep_half_split<<<1024, 256>>>(enc_w2, w2hp, w2lp, 262144);

    k_conv1<<<dim3(8, 128, 16), 128>>>(x, enc_w1, enc_b1);
    k_conv2_wmma<<<dim3(32, 16), 256, smem_c2>>>(enc_b2, enc_w3, enc_b3);
    k_vq<<<4096, 128>>>(cb, out);

    k_convt_wmma<64, 64, 64, false><<<dim3(2, 64, 16), 256, smem_dec>>>(
        zstp, wt1p, dec_b1, nullptr, nullptr, g1p);
    k_convt_wmma<128, 128, 128, true><<<dim3(4, 128, 16), 256, smem_dec>>>(
        g1p, wt2p, dec_b2, dec_w3, dec_b3, out);
    k_final<<<1, 1>>>(out);
}

// round 16
// speedup vs baseline: 3.5869x; 1.0661x over previous
#include <cuda_runtime.h>
#include <cuda_fp16.h>
#include <math.h>
#include <mma.h>

using namespace nvcuda;

// ---------------- sizes ----------------
#define BATCH 16
#define H0 256
#define W0 256
#define CIN 3
#define HID 128
#define EMB 64
#define KCODES 1024
#define H1v 128
#define W1v 128
#define H2v 64
#define W2v 64

#define XREC_ELEMS (BATCH*H0*W0*3)      // 3145728
#define TOK_OFF    XREC_ELEMS
#define TOK_ELEMS  (BATCH*H2v*W2v)      // 65536
#define LOSS_OFF   (TOK_OFF + TOK_ELEMS)

typedef unsigned long long u64;
typedef unsigned int u32;

// ---------------- scratch ----------------
__device__ __half g_h1h[BATCH*H1v*W1v*HID];   // conv1 out (gelu'd), fp16 high
__device__ __half g_h1l[BATCH*H1v*W1v*HID];   // fp16 low (residual)
__device__ float  g_ze[BATCH*H2v*W2v*EMB];    // z_e (fp32)
__device__ __half g_zsth[BATCH*H2v*W2v*EMB];  // z_st (half, for decoder MMA)
__device__ __half g_g1h[BATCH*H1v*W1v*HID];   // decoder convt1 out (half)
__device__ __half g_wt1h[1024*128];           // dec_w1 half
__device__ __half g_wt2h[2048*128];           // dec_w2 half
__device__ __half g_w2hh[2048*128];           // enc_w2 half high
__device__ __half g_w2ll[2048*128];           // enc_w2 half low
__device__ float  g_loss;

__device__ __forceinline__ float gelu_f(float x) {
    float t = 0.7978845608028654f * (x + 0.044715f * x * x * x);
    return 0.5f * x * (1.0f + tanhf(t));
}

// ---------------- packed f32x2 helpers ----------------
__device__ __forceinline__ u64 splat2(float a) {
    u64 r; asm("mov.b64 %0, {%1, %1};" : "=l"(r) : "f"(a)); return r;
}
__device__ __forceinline__ u64 pack2(float lo, float hi) {
    u64 r; asm("mov.b64 %0, {%1, %2};" : "=l"(r) : "f"(lo), "f"(hi)); return r;
}
__device__ __forceinline__ void unpack2(u64 v, float& lo, float& hi) {
    asm("mov.b64 {%0, %1}, %2;" : "=f"(lo), "=f"(hi) : "l"(v));
}
__device__ __forceinline__ void ffma2(u64& d, u64 a, u64 b) {
    asm("fma.rn.f32x2 %0, %1, %2, %0;" : "+l"(d) : "l"(a), "l"(b));
}

// ================= prep kernels =================
__global__ void k_prep_half(const float* __restrict__ w, __half* __restrict__ o, int n) {
    int i = blockIdx.x * 256 + threadIdx.x;
    if (i < n) o[i] = __float2half(w[i]);
}
__global__ void k_prep_half_split(const float* __restrict__ w, __half* __restrict__ oh,
                                  __half* __restrict__ ol, int n) {
    int i = blockIdx.x * 256 + threadIdx.x;
    if (i < n) {
        float a = w[i];
        __half h = __float2half(a);
        oh[i] = h;
        ol[i] = __float2half(a - __half2float(h));
    }
}
__global__ void k_zero_loss() { g_loss = 0.0f; }

// ================= conv1 WMMA fp16 3-product: x -> h1 (split fp16) =================
// M=128 px (one out row), N=128 co, K=48 (4ky*4kx*3ci) = 3 k-steps of 16.
// grid (128 oy, 16 n), block 256 = 8 warps (4m x 2n). occ 2.
// smem floats: xs[0,3120) Ah[3120,6704) Al[6704,10288) Bh[10288,13552) Bl[13552,16816)
//              Cs reuse [0,16896) bias[16896,17024)
__global__ void __launch_bounds__(256, 2) k_conv1_wmma(
    const float* __restrict__ x, const float* __restrict__ w,
    const float* __restrict__ b)
{
    extern __shared__ float smf[];
    float*  xs = smf;                                      // [4][260][3]
    __half* Ah = reinterpret_cast<__half*>(smf + 3120);    // [128][56] halves
    __half* Al = reinterpret_cast<__half*>(smf + 6704);    // [128][56]
    __half* Bh = reinterpret_cast<__half*>(smf + 10288);   // [48][136]
    __half* Bl = reinterpret_cast<__half*>(smf + 13552);   // [48][136]
    float*  Cs = smf;                                      // reuse [128][132]
    float*  bs = smf + 16896;

    int tid = threadIdx.x;
    int oy = blockIdx.x, n = blockIdx.y;

    for (int i = tid; i < 128; i += 256) bs[i] = b[i];
    // stage x rows 2oy-1..2oy+2, cols -1..256 (smem col c -> gx = c-1)
    for (int i = tid; i < 4*258*3; i += 256) {
        int r = i / (258*3); int rem = i - r*(258*3); int c = rem / 3; int ch = rem - c*3;
        int gy = 2*oy - 1 + r;
        int gx = c - 1;
        float v = 0.0f;
        if (gy >= 0 && gy < H0 && gx >= 0 && gx < W0) v = x[((n*H0+gy)*W0+gx)*CIN + ch];
        xs[r*780 + c*3 + ch] = v;
    }
    // stage B split: w is [48][128] row-major
    for (int i = tid; i < 48*128; i += 256) {
        int kk = i >> 7, co = i & 127;
        float a = w[i];
        __half h = __float2half(a);
        Bh[kk*136 + co] = h;
        Bl[kk*136 + co] = __float2half(a - __half2float(h));
    }
    __syncthreads();
    // build A split: A[m][k], k = (ky*4+kx)*3+ci, value = xs[ky][2m+kx][ci]
    for (int i = tid; i < 128*48; i += 256) {
        int m = i / 48, k = i - m*48;
        int ky = k / 12; int kx = (k / 3) & 3; int ci = k - ky*12 - kx*3;
        float v = xs[ky*780 + (2*m + kx)*3 + ci];
        __half h = __float2half(v);
        Ah[m*56 + k] = h;
        Al[m*56 + k] = __float2half(v - __half2float(h));
    }
    __syncthreads();

    int wid = tid >> 5;
    int m0 = (wid & 3) * 32;
    int n0 = (wid >> 2) * 64;
    wmma::fragment<wmma::accumulator, 16, 16, 16, float> acc[2][4];
#pragma unroll
    for (int im = 0; im < 2; im++)
#pragma unroll
        for (int in = 0; in < 4; in++) wmma::fill_fragment(acc[im][in], 0.0f);
#pragma unroll
    for (int ks = 0; ks < 3; ks++) {
        int kk = ks * 16;
        wmma::fragment<wmma::matrix_a, 16, 16, 16, __half, wmma::row_major> ahf[2], alf[2];
#pragma unroll
        for (int im = 0; im < 2; im++) {
            wmma::load_matrix_sync(ahf[im], &Ah[(m0 + 16*im)*56 + kk], 56);
            wmma::load_matrix_sync(alf[im], &Al[(m0 + 16*im)*56 + kk], 56);
        }
#pragma unroll
        for (int in = 0; in < 4; in++) {
            wmma::fragment<wmma::matrix_b, 16, 16, 16, __half, wmma::row_major> bhf, blf;
            wmma::load_matrix_sync(bhf, &Bh[kk*136 + n0 + 16*in], 136);
            wmma::load_matrix_sync(blf, &Bl[kk*136 + n0 + 16*in], 136);
#pragma unroll
            for (int im = 0; im < 2; im++) {
                wmma::mma_sync(acc[im][in], alf[im], bhf, acc[im][in]);
                wmma::mma_sync(acc[im][in], ahf[im], blf, acc[im][in]);
                wmma::mma_sync(acc[im][in], ahf[im], bhf, acc[im][in]);
            }
        }
    }
    __syncthreads();
#pragma unroll
    for (int im = 0; im < 2; im++)
#pragma unroll
        for (int in = 0; in < 4; in++)
            wmma::store_matrix_sync(&Cs[(m0 + 16*im)*132 + n0 + 16*in],
                                    acc[im][in], 132, wmma::mem_row_major);
    __syncthreads();
    // bias + gelu + split-store
    for (int i = tid; i < 128*128; i += 256) {
        int px = i >> 7, co = i & 127;
        float g = gelu_f(Cs[px*132 + co] + bs[co]);
        size_t go = (size_t)((n*H1v + oy)*W1v + px)*HID + co;
        __half h = __float2half(g);
        g_h1h[go] = h;
        g_h1l[go] = __float2half(g - __half2float(h));
    }
}

// ================= conv2 WMMA fp16 3-product + gelu + 1x1: h1 -> z_e =================
__global__ void __launch_bounds__(256, 2) k_conv2_wmma(
    const float* __restrict__ b2,
    const float* __restrict__ w3, const float* __restrict__ b3)
{
    extern __shared__ float smf[];
    __half* Ah = reinterpret_cast<__half*>(smf);            // [128][72]
    __half* Al = reinterpret_cast<__half*>(smf + 4608);     // [128][72]
    __half* Bh = reinterpret_cast<__half*>(smf + 9216);     // [64][136]
    __half* Bl = reinterpret_cast<__half*>(smf + 13568);    // [64][136]
    float* Cs  = smf;                                       // reuse [128][132]
    float* b2s = smf + 17920;
    float* b3s = smf + 18048;

    int tid = threadIdx.x;
    int pr = blockIdx.x, n = blockIdx.y;
    int oy0 = pr * 2;

    for (int i = tid; i < 128; i += 256) b2s[i] = b2[i];
    if (tid < 64) b3s[tid] = b3[tid];

    int wid = tid >> 5;
    int m0 = (wid & 3) * 32;
    int n0 = (wid >> 2) * 64;

    wmma::fragment<wmma::accumulator, 16, 16, 16, float> acc[2][4];
#pragma unroll
    for (int im = 0; im < 2; im++)
#pragma unroll
        for (int in = 0; in < 4; in++) wmma::fill_fragment(acc[im][in], 0.0f);

#pragma unroll 1
    for (int c = 0; c < 32; c++) {
        int tap = c >> 1;
        int ci0 = (c & 1) * 64;
        int ky = tap >> 2, kx = tap & 3;
        __syncthreads();
#pragma unroll
        for (int q = 0; q < 4; q++) {
            int u = tid + q*256;
            int m = u >> 3, c8 = u & 7;
            int h = m >> 6, j = m & 63;
            int iy = 2*(oy0 + h) - 1 + ky;
            int ix = 2*j - 1 + kx;
            uint4 vh = make_uint4(0,0,0,0), vl = make_uint4(0,0,0,0);
            if (iy >= 0 && iy < H1v && ix >= 0 && ix < W1v) {
                size_t go = ((size_t)((n*H1v + iy)*W1v + ix))*HID + ci0 + 8*c8;
                vh = *reinterpret_cast<const uint4*>(&g_h1h[go]);
                vl = *reinterpret_cast<const uint4*>(&g_h1l[go]);
            }
            *reinterpret_cast<uint4*>(&Ah[m*72 + 8*c8]) = vh;
            *reinterpret_cast<uint4*>(&Al[m*72 + 8*c8]) = vl;
        }
#pragma unroll
        for (int q = 0; q < 4; q++) {
            int u = tid + q*256;
            int kk = u >> 4, c16 = u & 15;
            size_t go = ((size_t)(tap*HID + ci0 + kk))*128 + 8*c16;
            *reinterpret_cast<uint4*>(&Bh[kk*136 + 8*c16]) =
                *reinterpret_cast<const uint4*>(&g_w2hh[go]);
            *reinterpret_cast<uint4*>(&Bl[kk*136 + 8*c16]) =
                *reinterpret_cast<const uint4*>(&g_w2ll[go]);
        }
        __syncthreads();
#pragma unroll
        for (int ks = 0; ks < 4; ks++) {
            int kk = ks * 16;
            wmma::fragment<wmma::matrix_a, 16, 16, 16, __half, wmma::row_major> ahf[2], alf[2];
#pragma unroll
            for (int im = 0; im < 2; im++) {
                wmma::load_matrix_sync(ahf[im], &Ah[(m0 + 16*im)*72 + kk], 72);
                wmma::load_matrix_sync(alf[im], &Al[(m0 + 16*im)*72 + kk], 72);
            }
#pragma unroll
            for (int in = 0; in < 4; in++) {
                wmma::fragment<wmma::matrix_b, 16, 16, 16, __half, wmma::row_major> bhf, blf;
                wmma::load_matrix_sync(bhf, &Bh[kk*136 + n0 + 16*in], 136);
                wmma::load_matrix_sync(blf, &Bl[kk*136 + n0 + 16*in], 136);
#pragma unroll
                for (int im = 0; im < 2; im++) {
                    wmma::mma_sync(acc[im][in], alf[im], bhf, acc[im][in]);
                    wmma::mma_sync(acc[im][in], ahf[im], blf, acc[im][in]);
                    wmma::mma_sync(acc[im][in], ahf[im], bhf, acc[im][in]);
                }
            }
        }
    }
    __syncthreads();
#pragma unroll
    for (int im = 0; im < 2; im++)
#pragma unroll
        for (int in = 0; in < 4; in++)
            wmma::store_matrix_sync(&Cs[(m0 + 16*im)*132 + n0 + 16*in],
                                    acc[im][in], 132, wmma::mem_row_major);
    __syncthreads();
    for (int i = tid; i < 128*128; i += 256) {
        int px = i >> 7, ci = i & 127;
        Cs[px*132 + ci] = gelu_f(Cs[px*132 + ci] + b2s[ci]);
    }
    __syncthreads();
    {
        int px = tid >> 1;
        int e0 = (tid & 1) * 32;
        u64 z2[16];
#pragma unroll
        for (int u = 0; u < 8; u++) {
            z2[2*u]   = pack2(b3s[e0 + 4*u],     b3s[e0 + 4*u + 1]);
            z2[2*u+1] = pack2(b3s[e0 + 4*u + 2], b3s[e0 + 4*u + 3]);
        }
#pragma unroll 4
        for (int ci = 0; ci < 128; ci++) {
            float hv = Cs[px*132 + ci];
            u64 s = splat2(hv);
#pragma unroll
            for (int u = 0; u < 8; u++) {
                float4 wv = *reinterpret_cast<const float4*>(&w3[ci*EMB + e0 + 4*u]);
                ffma2(z2[2*u],   s, pack2(wv.x, wv.y));
                ffma2(z2[2*u+1], s, pack2(wv.z, wv.w));
            }
        }
        int row = oy0 + (px >> 6), col = px & 63;
        float* dst = &g_ze[((size_t)((n*H2v + row)*W2v + col))*EMB + e0];
#pragma unroll
        for (int u = 0; u < 8; u++) {
            float f0,f1,f2,f3;
            unpack2(z2[2*u], f0, f1); unpack2(z2[2*u+1], f2, f3);
            *reinterpret_cast<float4*>(dst + 4*u) = make_float4(f0, f1, f2, f3);
        }
    }
}

// ================= VQ (fp32; writes z_st as half for decoder) =================
#define CSTR 68
__global__ void k_vq(const float* __restrict__ cb, float* __restrict__ dout) {
    __shared__ float cs[64*CSTR];
    __shared__ float e2s[64];
    __shared__ float bval[128];
    __shared__ int   bidx[128];
    __shared__ int   widx[16];
    __shared__ float lred[128];
    int tid = threadIdx.x;
    int pb = blockIdx.x * 16;
    int p = tid & 15;
    int g = tid >> 4;
    float4 z4[16];
    const float* zp = &g_ze[(pb + p)*EMB];
#pragma unroll
    for (int i = 0; i < 16; i++) z4[i] = *reinterpret_cast<const float4*>(&zp[4*i]);
    float best = 3.4e38f; int bi = 0;
    for (int ch = 0; ch < 16; ch++) {
        for (int i = tid; i < 64*16; i += 128) {
            int cj = i >> 4; int d4 = i & 15;
            float4 v = *reinterpret_cast<const float4*>(&cb[(ch*64+cj)*EMB + 4*d4]);
            *reinterpret_cast<float4*>(&cs[cj*CSTR + 4*d4]) = v;
        }
        __syncthreads();
        if (tid < 64) {
            float s = 0.0f;
#pragma unroll 8
            for (int d = 0; d < 64; d++) { float c = cs[tid*CSTR + d]; s = fmaf(c, c, s); }
            e2s[tid] = s;
        }
        __syncthreads();
#pragma unroll
        for (int j = 0; j < 8; j++) {
            int cj = g*8 + j;
            const float* cp = &cs[cj*CSTR];
            float dot = 0.0f;
#pragma unroll
            for (int i = 0; i < 16; i++) {
                float4 c = *reinterpret_cast<const float4*>(&cp[4*i]);
                dot = fmaf(z4[i].x, c.x, dot); dot = fmaf(z4[i].y, c.y, dot);
                dot = fmaf(z4[i].z, c.z, dot); dot = fmaf(z4[i].w, c.w, dot);
            }
            float dist = e2s[cj] - 2.0f*dot;
            int gidx = ch*64 + cj;
            if (dist < best || (dist == best && gidx < bi)) { best = dist; bi = gidx; }
        }
        __syncthreads();
    }
    bval[tid] = best; bidx[tid] = bi;
    __syncthreads();
    if (tid < 16) {
        float bb = bval[tid]; int bbi = bidx[tid];
        for (int k = 1; k < 8; k++) {
            float v = bval[tid + 16*k]; int vi = bidx[tid + 16*k];
            if (v < bb || (v == bb && vi < bbi)) { bb = v; bbi = vi; }
        }
        widx[tid] = bbi;
        dout[TOK_OFF + pb + tid] = (float)bbi;
    }
    __syncthreads();
    int idx = widx[p];
    float lsum = 0.0f;
    const float* cq = &cb[idx*EMB + g*8];
    const float* ze = &g_ze[(pb + p)*EMB + g*8];
    __half*      zs = &g_zsth[(pb + p)*EMB + g*8];
#pragma unroll
    for (int d = 0; d < 8; d++) {
        float zq = cq[d]; float z = ze[d];
        float diff = zq - z;
        zs[d] = __float2half(z + diff);
        lsum = fmaf(diff, diff, lsum);
    }
    lred[tid] = lsum;
    __syncthreads();
    for (int s = 64; s > 0; s >>= 1) {
        if (tid < s) lred[tid] += lred[tid + s];
        __syncthreads();
    }
    if (tid == 0) atomicAdd(&g_loss, lred[0]);
}

// ================= WMMA fp16 transposed-conv (reg-prefetch pipelined) =====
template<int CI, int HIN, int WIN, bool RGB>
__global__ void __launch_bounds__(256, 2) k_convt_wmma(
    const __half* __restrict__ src, const __half* __restrict__ wt,
    const float* __restrict__ bias,
    const float* __restrict__ w3, const float* __restrict__ b3,
    void* __restrict__ dstv)
{
    constexpr int CIC64 = CI / 64;
    constexpr int NCH   = 4 * CIC64;
    constexpr int HOUT  = 2 * HIN;
    constexpr int WOUT  = 2 * WIN;

    extern __shared__ float smf[];
    __half* As   = reinterpret_cast<__half*>(smf);          // [128][72]
    __half* Bs   = reinterpret_cast<__half*>(smf + 4608);   // [64][136]
    float* Cs    = smf;             // epilogue reuse
    float* biass = smf + 17152;
    float* w3s   = smf + 17280;
    float* b3s   = smf + 17664;

    int tid = threadIdx.x;
    int bx = blockIdx.x, pr = blockIdx.y, n = blockIdx.z;
    int t  = bx & 1;
    int xh = bx >> 1;
    int oy = 4*(pr >> 1) + (pr & 1);
    int x0 = xh * 128;
    int xhalf = x0 >> 1;
    int kyA = oy & 1;
    int iy0 = (oy + kyA - 2) >> 1;

    for (int i = tid; i < 128; i += 256) biass[i] = bias[i];
    if (RGB) {
        for (int i = tid; i < 384; i += 256) w3s[i] = w3[i];
        if (tid < 3) b3s[tid] = b3[tid];
    }

    int wid = tid >> 5;
    int m0 = (wid & 3) * 32;
    int n0 = (wid >> 2) * 64;

    wmma::fragment<wmma::accumulator, 16, 16, 16, float> acc[2][4];
#pragma unroll
    for (int im = 0; im < 2; im++)
#pragma unroll
        for (int in = 0; in < 4; in++) wmma::fill_fragment(acc[im][in], 0.0f);

    uint4 pa[4], pb[4];
    auto ldg_chunk = [&](int c) {
        int kyi = c / (2*CIC64);
        int kxi = (c / CIC64) & 1;
        int ci0 = (c % CIC64) * 64;
        int xb = xhalf + t + kxi - 1;
#pragma unroll
        for (int q = 0; q < 4; q++) {
            int u = tid + q*256;
            int m = u >> 3, c8 = u & 7;
            int h = m >> 6, j = m & 63;
            int y = iy0 + h + kyi;
            int col = xb + j;
            uint4 v = make_uint4(0,0,0,0);
            if (y >= 0 && y < HIN && col >= 0 && col < WIN)
                v = *reinterpret_cast<const uint4*>(
                    &src[((size_t)((n*HIN + y)*WIN + col))*CI + ci0 + 8*c8]);
            pa[q] = v;
        }
        int k0 = ((kyA + 2*kyi)*4 + (t + 2*kxi))*CI + ci0;
#pragma unroll
        for (int q = 0; q < 4; q++) {
            int u = tid + q*256;
            int kk = u >> 4, c16 = u & 15;
            pb[q] = *reinterpret_cast<const uint4*>(&wt[(size_t)(k0 + kk)*128 + 8*c16]);
        }
    };
    auto sts_chunk = [&]() {
#pragma unroll
        for (int q = 0; q < 4; q++) {
            int u = tid + q*256;
            int m = u >> 3, c8 = u & 7;
            *reinterpret_cast<uint4*>(&As[m*72 + 8*c8]) = pa[q];
        }
#pragma unroll
        for (int q = 0; q < 4; q++) {
            int u = tid + q*256;
            int kk = u >> 4, c16 = u & 15;
            *reinterpret_cast<uint4*>(&Bs[kk*136 + 8*c16]) = pb[q];
        }
    };

    ldg_chunk(0);
    sts_chunk();
    __syncthreads();
#pragma unroll 1
    for (int c = 0; c < NCH; c++) {
        if (c + 1 < NCH) ldg_chunk(c + 1);
#pragma unroll
        for (int ks = 0; ks < 4; ks++) {
            int kk = ks * 16;
            wmma::fragment<wmma::matrix_a, 16, 16, 16, __half, wmma::row_major> af[2];
#pragma unroll
            for (int im = 0; im < 2; im++)
                wmma::load_matrix_sync(af[im], &As[(m0 + 16*im)*72 + kk], 72);
#pragma unroll
            for (int in = 0; in < 4; in++) {
                wmma::fragment<wmma::matrix_b, 16, 16, 16, __half, wmma::row_major> bf;
                wmma::load_matrix_sync(bf, &Bs[kk*136 + n0 + 16*in], 136);
#pragma unroll
                for (int im = 0; im < 2; im++)
                    wmma::mma_sync(acc[im][in], af[im], bf, acc[im][in]);
            }
        }
        __syncthreads();
        if (c + 1 < NCH) {
            sts_chunk();
        }
        __syncthreads();
    }
#pragma unroll
    for (int im = 0; im < 2; im++)
#pragma unroll
        for (int in = 0; in < 4; in++)
            wmma::store_matrix_sync(&Cs[(m0 + 16*im)*132 + n0 + 16*in],
                                    acc[im][in], 132, wmma::mem_row_major);
    __syncthreads();
    // epilogue
    {
        int m = tid >> 1;
        int half = tid & 1;
        int h = m >> 6, j = m & 63;
        int row = oy + 2*h;
        int ox = x0 + 2*j + t;
        const float* cp = &Cs[m*132 + half*64];
        if (RGB) {
            float* dst = reinterpret_cast<float*>(dstv);
            float r = 0.0f, g = 0.0f, bl = 0.0f;
#pragma unroll 8
            for (int kk = 0; kk < 64; kk++) {
                int cc = half*64 + kk;
                float gv = gelu_f(cp[kk] + biass[cc]);
                r  = fmaf(gv, w3s[cc*3+0], r);
                g  = fmaf(gv, w3s[cc*3+1], g);
                bl = fmaf(gv, w3s[cc*3+2], bl);
            }
            r  += __shfl_xor_sync(0xffffffffu, r, 1);
            g  += __shfl_xor_sync(0xffffffffu, g, 1);
            bl += __shfl_xor_sync(0xffffffffu, bl, 1);
            if (half == 0) {
                float* dp = dst + ((size_t)((n*HOUT + row)*WOUT + ox))*3;
                dp[0] = r + b3s[0];
                dp[1] = g + b3s[1];
                dp[2] = bl + b3s[2];
            }
        } else {
            __half* dst = reinterpret_cast<__half*>(dstv);
            __half* dp = dst + ((size_t)((n*HOUT + row)*WOUT + ox))*128 + half*64;
#pragma unroll
            for (int k2 = 0; k2 < 32; k2++) {
                float a = gelu_f(cp[2*k2+0] + biass[half*64 + 2*k2+0]);
                float b = gelu_f(cp[2*k2+1] + biass[half*64 + 2*k2+1]);
                *reinterpret_cast<__half2*>(dp + 2*k2) = __floats2half2_rn(a, b);
            }
        }
    }
}

// ================= finalize losses =================
__global__ void k_final(float* __restrict__ dout) {
    float l = g_loss / (float)(TOK_ELEMS * EMB);
    dout[LOSS_OFF]     = l;
    dout[LOSS_OFF + 1] = l;
}

// ================= launch =================
extern "C" void kernel_launch(void* const* d_in, const int* in_sizes, int n_in,
                              void* d_out, int out_size) {
    const float* x      = (const float*)d_in[0];
    const float* enc_w1 = (const float*)d_in[1];
    const float* enc_b1 = (const float*)d_in[2];
    const float* enc_w2 = (const float*)d_in[3];
    const float* enc_b2 = (const float*)d_in[4];
    const float* enc_w3 = (const float*)d_in[5];
    const float* enc_b3 = (const float*)d_in[6];
    const float* cb     = (const float*)d_in[7];
    const float* dec_w1 = (const float*)d_in[8];
    const float* dec_b1 = (const float*)d_in[9];
    const float* dec_w2 = (const float*)d_in[10];
    const float* dec_b2 = (const float*)d_in[11];
    const float* dec_w3 = (const float*)d_in[12];
    const float* dec_b3 = (const float*)d_in[13];
    float* out = (float*)d_out;

    __half* wt1p; cudaGetSymbolAddress((void**)&wt1p, g_wt1h);
    __half* wt2p; cudaGetSymbolAddress((void**)&wt2p, g_wt2h);
    __half* zstp; cudaGetSymbolAddress((void**)&zstp, g_zsth);
    __half* g1p;  cudaGetSymbolAddress((void**)&g1p, g_g1h);
    __half* w2hp; cudaGetSymbolAddress((void**)&w2hp, g_w2hh);
    __half* w2lp; cudaGetSymbolAddress((void**)&w2lp, g_w2ll);

    const int smem_dec = 17667 * 4;   // 70668 B (occ 2)
    const int smem_c2  = 18112 * 4;   // 72448 B (occ 2)
    const int smem_c1  = 17024 * 4;   // 68096 B (occ 2)
    static int smem_set = 0;
    if (!smem_set) {
        cudaFuncSetAttribute(k_convt_wmma<64, 64, 64, false>,
                             cudaFuncAttributeMaxDynamicSharedMemorySize, smem_dec);
        cudaFuncSetAttribute(k_convt_wmma<128, 128, 128, true>,
                             cudaFuncAttributeMaxDynamicSharedMemorySize, smem_dec);
        cudaFuncSetAttribute(k_conv2_wmma,
                             cudaFuncAttributeMaxDynamicSharedMemorySize, smem_c2);
        cudaFuncSetAttribute(k_conv1_wmma,
                             cudaFuncAttributeMaxDynamicSharedMemorySize, smem_c1);
        smem_set = 1;
    }

    k_zero_loss<<<1, 1>>>();
    k_prep_half<<<512, 256>>>(dec_w1, wt1p, 131072);
    k_prep_half<<<1024, 256>>>(dec_w2, wt2p, 262144);
    k_prep_half_split<<<1024, 256>>>(enc_w2, w2hp, w2lp, 262144);

    k_conv1_wmma<<<dim3(128, 16), 256, smem_c1>>>(x, enc_w1, enc_b1);
    k_conv2_wmma<<<dim3(32, 16), 256, smem_c2>>>(enc_b2, enc_w3, enc_b3);
    k_vq<<<4096, 128>>>(cb, out);

    k_convt_wmma<64, 64, 64, false><<<dim3(2, 64, 16), 256, smem_dec>>>(
        zstp, wt1p, dec_b1, nullptr, nullptr, g1p);
    k_convt_wmma<128, 128, 128, true><<<dim3(4, 128, 16), 256, smem_dec>>>(
        g1p, wt2p, dec_b2, dec_w3, dec_b3, out);
    k_final<<<1, 1>>>(out);
}

// round 17
// speedup vs baseline: 4.1994x; 1.1707x over previous
#include <cuda_runtime.h>
#include <cuda_fp16.h>
#include <math.h>
#include <mma.h>

using namespace nvcuda;

// ---------------- sizes ----------------
#define BATCH 16
#define H0 256
#define W0 256
#define CIN 3
#define HID 128
#define EMB 64
#define KCODES 1024
#define H1v 128
#define W1v 128
#define H2v 64
#define W2v 64

#define XREC_ELEMS (BATCH*H0*W0*3)      // 3145728
#define TOK_OFF    XREC_ELEMS
#define TOK_ELEMS  (BATCH*H2v*W2v)      // 65536
#define LOSS_OFF   (TOK_OFF + TOK_ELEMS)

typedef unsigned long long u64;
typedef unsigned int u32;

// ---------------- scratch ----------------
__device__ __half g_h1h[BATCH*H1v*W1v*HID];   // conv1 out (gelu'd), fp16 high
__device__ __half g_h1l[BATCH*H1v*W1v*HID];   // fp16 low (residual)
__device__ float  g_ze[BATCH*H2v*W2v*EMB];    // z_e (fp32)
__device__ __half g_zsth[BATCH*H2v*W2v*EMB];  // z_st (half, for decoder MMA)
__device__ __half g_g1h[BATCH*H1v*W1v*HID];   // decoder convt1 out (half)
__device__ __half g_wt1h[1024*128];           // dec_w1 half
__device__ __half g_wt2h[2048*128];           // dec_w2 half
__device__ __half g_w2hh[2048*128];           // enc_w2 half high
__device__ __half g_w2ll[2048*128];           // enc_w2 half low
__device__ __half g_cbh[KCODES*EMB];          // codebook half high
__device__ __half g_cbl[KCODES*EMB];          // codebook half low
__device__ float  g_e2[KCODES];               // codebook squared norms
__device__ float  g_loss;

__device__ __forceinline__ float gelu_f(float x) {
    float t = 0.7978845608028654f * (x + 0.044715f * x * x * x);
    return 0.5f * x * (1.0f + tanhf(t));
}

// ---------------- packed f32x2 helpers ----------------
__device__ __forceinline__ u64 splat2(float a) {
    u64 r; asm("mov.b64 %0, {%1, %1};" : "=l"(r) : "f"(a)); return r;
}
__device__ __forceinline__ u64 pack2(float lo, float hi) {
    u64 r; asm("mov.b64 %0, {%1, %2};" : "=l"(r) : "f"(lo), "f"(hi)); return r;
}
__device__ __forceinline__ void unpack2(u64 v, float& lo, float& hi) {
    asm("mov.b64 {%0, %1}, %2;" : "=f"(lo), "=f"(hi) : "l"(v));
}
__device__ __forceinline__ void ffma2(u64& d, u64 a, u64 b) {
    asm("fma.rn.f32x2 %0, %1, %2, %0;" : "+l"(d) : "l"(a), "l"(b));
}

// ================= prep kernels =================
__global__ void k_prep_half(const float* __restrict__ w, __half* __restrict__ o, int n) {
    int i = blockIdx.x * 256 + threadIdx.x;
    if (i < n) o[i] = __float2half(w[i]);
}
__global__ void k_prep_half_split(const float* __restrict__ w, __half* __restrict__ oh,
                                  __half* __restrict__ ol, int n) {
    int i = blockIdx.x * 256 + threadIdx.x;
    if (i < n) {
        float a = w[i];
        __half h = __float2half(a);
        oh[i] = h;
        ol[i] = __float2half(a - __half2float(h));
    }
}
__global__ void k_prep_e2(const float* __restrict__ cb) {
    int c = blockIdx.x * 256 + threadIdx.x;
    if (c < KCODES) {
        float s = 0.0f;
        const float* p = &cb[c*EMB];
#pragma unroll 8
        for (int d = 0; d < EMB; d++) s = fmaf(p[d], p[d], s);
        g_e2[c] = s;
    }
}
__global__ void k_zero_loss() { g_loss = 0.0f; }

// ================= conv1 WMMA fp16 3-product: x -> h1 (split fp16) =================
__global__ void __launch_bounds__(256, 2) k_conv1_wmma(
    const float* __restrict__ x, const float* __restrict__ w,
    const float* __restrict__ b)
{
    extern __shared__ float smf[];
    float*  xs = smf;                                      // [4][260][3]
    __half* Ah = reinterpret_cast<__half*>(smf + 3120);    // [128][56] halves
    __half* Al = reinterpret_cast<__half*>(smf + 6704);    // [128][56]
    __half* Bh = reinterpret_cast<__half*>(smf + 10288);   // [48][136]
    __half* Bl = reinterpret_cast<__half*>(smf + 13552);   // [48][136]
    float*  Cs = smf;                                      // reuse [128][132]
    float*  bs = smf + 16896;

    int tid = threadIdx.x;
    int oy = blockIdx.x, n = blockIdx.y;

    for (int i = tid; i < 128; i += 256) bs[i] = b[i];
    for (int i = tid; i < 4*258*3; i += 256) {
        int r = i / (258*3); int rem = i - r*(258*3); int c = rem / 3; int ch = rem - c*3;
        int gy = 2*oy - 1 + r;
        int gx = c - 1;
        float v = 0.0f;
        if (gy >= 0 && gy < H0 && gx >= 0 && gx < W0) v = x[((n*H0+gy)*W0+gx)*CIN + ch];
        xs[r*780 + c*3 + ch] = v;
    }
    for (int i = tid; i < 48*128; i += 256) {
        int kk = i >> 7, co = i & 127;
        float a = w[i];
        __half h = __float2half(a);
        Bh[kk*136 + co] = h;
        Bl[kk*136 + co] = __float2half(a - __half2float(h));
    }
    __syncthreads();
    for (int i = tid; i < 128*48; i += 256) {
        int m = i / 48, k = i - m*48;
        int ky = k / 12; int kx = (k / 3) & 3; int ci = k - ky*12 - kx*3;
        float v = xs[ky*780 + (2*m + kx)*3 + ci];
        __half h = __float2half(v);
        Ah[m*56 + k] = h;
        Al[m*56 + k] = __float2half(v - __half2float(h));
    }
    __syncthreads();

    int wid = tid >> 5;
    int m0 = (wid & 3) * 32;
    int n0 = (wid >> 2) * 64;
    wmma::fragment<wmma::accumulator, 16, 16, 16, float> acc[2][4];
#pragma unroll
    for (int im = 0; im < 2; im++)
#pragma unroll
        for (int in = 0; in < 4; in++) wmma::fill_fragment(acc[im][in], 0.0f);
#pragma unroll
    for (int ks = 0; ks < 3; ks++) {
        int kk = ks * 16;
        wmma::fragment<wmma::matrix_a, 16, 16, 16, __half, wmma::row_major> ahf[2], alf[2];
#pragma unroll
        for (int im = 0; im < 2; im++) {
            wmma::load_matrix_sync(ahf[im], &Ah[(m0 + 16*im)*56 + kk], 56);
            wmma::load_matrix_sync(alf[im], &Al[(m0 + 16*im)*56 + kk], 56);
        }
#pragma unroll
        for (int in = 0; in < 4; in++) {
            wmma::fragment<wmma::matrix_b, 16, 16, 16, __half, wmma::row_major> bhf, blf;
            wmma::load_matrix_sync(bhf, &Bh[kk*136 + n0 + 16*in], 136);
            wmma::load_matrix_sync(blf, &Bl[kk*136 + n0 + 16*in], 136);
#pragma unroll
            for (int im = 0; im < 2; im++) {
                wmma::mma_sync(acc[im][in], alf[im], bhf, acc[im][in]);
                wmma::mma_sync(acc[im][in], ahf[im], blf, acc[im][in]);
                wmma::mma_sync(acc[im][in], ahf[im], bhf, acc[im][in]);
            }
        }
    }
    __syncthreads();
#pragma unroll
    for (int im = 0; im < 2; im++)
#pragma unroll
        for (int in = 0; in < 4; in++)
            wmma::store_matrix_sync(&Cs[(m0 + 16*im)*132 + n0 + 16*in],
                                    acc[im][in], 132, wmma::mem_row_major);
    __syncthreads();
    for (int i = tid; i < 128*128; i += 256) {
        int px = i >> 7, co = i & 127;
        float g = gelu_f(Cs[px*132 + co] + bs[co]);
        size_t go = (size_t)((n*H1v + oy)*W1v + px)*HID + co;
        __half h = __float2half(g);
        g_h1h[go] = h;
        g_h1l[go] = __float2half(g - __half2float(h));
    }
}

// ================= conv2 WMMA fp16 3-product + gelu + 1x1: h1 -> z_e =================
__global__ void __launch_bounds__(256, 2) k_conv2_wmma(
    const float* __restrict__ b2,
    const float* __restrict__ w3, const float* __restrict__ b3)
{
    extern __shared__ float smf[];
    __half* Ah = reinterpret_cast<__half*>(smf);            // [128][72]
    __half* Al = reinterpret_cast<__half*>(smf + 4608);     // [128][72]
    __half* Bh = reinterpret_cast<__half*>(smf + 9216);     // [64][136]
    __half* Bl = reinterpret_cast<__half*>(smf + 13568);    // [64][136]
    float* Cs  = smf;                                       // reuse [128][132]
    float* b2s = smf + 17920;
    float* b3s = smf + 18048;

    int tid = threadIdx.x;
    int pr = blockIdx.x, n = blockIdx.y;
    int oy0 = pr * 2;

    for (int i = tid; i < 128; i += 256) b2s[i] = b2[i];
    if (tid < 64) b3s[tid] = b3[tid];

    int wid = tid >> 5;
    int m0 = (wid & 3) * 32;
    int n0 = (wid >> 2) * 64;

    wmma::fragment<wmma::accumulator, 16, 16, 16, float> acc[2][4];
#pragma unroll
    for (int im = 0; im < 2; im++)
#pragma unroll
        for (int in = 0; in < 4; in++) wmma::fill_fragment(acc[im][in], 0.0f);

#pragma unroll 1
    for (int c = 0; c < 32; c++) {
        int tap = c >> 1;
        int ci0 = (c & 1) * 64;
        int ky = tap >> 2, kx = tap & 3;
        __syncthreads();
#pragma unroll
        for (int q = 0; q < 4; q++) {
            int u = tid + q*256;
            int m = u >> 3, c8 = u & 7;
            int h = m >> 6, j = m & 63;
            int iy = 2*(oy0 + h) - 1 + ky;
            int ix = 2*j - 1 + kx;
            uint4 vh = make_uint4(0,0,0,0), vl = make_uint4(0,0,0,0);
            if (iy >= 0 && iy < H1v && ix >= 0 && ix < W1v) {
                size_t go = ((size_t)((n*H1v + iy)*W1v + ix))*HID + ci0 + 8*c8;
                vh = *reinterpret_cast<const uint4*>(&g_h1h[go]);
                vl = *reinterpret_cast<const uint4*>(&g_h1l[go]);
            }
            *reinterpret_cast<uint4*>(&Ah[m*72 + 8*c8]) = vh;
            *reinterpret_cast<uint4*>(&Al[m*72 + 8*c8]) = vl;
        }
#pragma unroll
        for (int q = 0; q < 4; q++) {
            int u = tid + q*256;
            int kk = u >> 4, c16 = u & 15;
            size_t go = ((size_t)(tap*HID + ci0 + kk))*128 + 8*c16;
            *reinterpret_cast<uint4*>(&Bh[kk*136 + 8*c16]) =
                *reinterpret_cast<const uint4*>(&g_w2hh[go]);
            *reinterpret_cast<uint4*>(&Bl[kk*136 + 8*c16]) =
                *reinterpret_cast<const uint4*>(&g_w2ll[go]);
        }
        __syncthreads();
#pragma unroll
        for (int ks = 0; ks < 4; ks++) {
            int kk = ks * 16;
            wmma::fragment<wmma::matrix_a, 16, 16, 16, __half, wmma::row_major> ahf[2], alf[2];
#pragma unroll
            for (int im = 0; im < 2; im++) {
                wmma::load_matrix_sync(ahf[im], &Ah[(m0 + 16*im)*72 + kk], 72);
                wmma::load_matrix_sync(alf[im], &Al[(m0 + 16*im)*72 + kk], 72);
            }
#pragma unroll
            for (int in = 0; in < 4; in++) {
                wmma::fragment<wmma::matrix_b, 16, 16, 16, __half, wmma::row_major> bhf, blf;
                wmma::load_matrix_sync(bhf, &Bh[kk*136 + n0 + 16*in], 136);
                wmma::load_matrix_sync(blf, &Bl[kk*136 + n0 + 16*in], 136);
#pragma unroll
                for (int im = 0; im < 2; im++) {
                    wmma::mma_sync(acc[im][in], alf[im], bhf, acc[im][in]);
                    wmma::mma_sync(acc[im][in], ahf[im], blf, acc[im][in]);
                    wmma::mma_sync(acc[im][in], ahf[im], bhf, acc[im][in]);
                }
            }
        }
    }
    __syncthreads();
#pragma unroll
    for (int im = 0; im < 2; im++)
#pragma unroll
        for (int in = 0; in < 4; in++)
            wmma::store_matrix_sync(&Cs[(m0 + 16*im)*132 + n0 + 16*in],
                                    acc[im][in], 132, wmma::mem_row_major);
    __syncthreads();
    for (int i = tid; i < 128*128; i += 256) {
        int px = i >> 7, ci = i & 127;
        Cs[px*132 + ci] = gelu_f(Cs[px*132 + ci] + b2s[ci]);
    }
    __syncthreads();
    {
        int px = tid >> 1;
        int e0 = (tid & 1) * 32;
        u64 z2[16];
#pragma unroll
        for (int u = 0; u < 8; u++) {
            z2[2*u]   = pack2(b3s[e0 + 4*u],     b3s[e0 + 4*u + 1]);
            z2[2*u+1] = pack2(b3s[e0 + 4*u + 2], b3s[e0 + 4*u + 3]);
        }
#pragma unroll 4
        for (int ci = 0; ci < 128; ci++) {
            float hv = Cs[px*132 + ci];
            u64 s = splat2(hv);
#pragma unroll
            for (int u = 0; u < 8; u++) {
                float4 wv = *reinterpret_cast<const float4*>(&w3[ci*EMB + e0 + 4*u]);
                ffma2(z2[2*u],   s, pack2(wv.x, wv.y));
                ffma2(z2[2*u+1], s, pack2(wv.z, wv.w));
            }
        }
        int row = oy0 + (px >> 6), col = px & 63;
        float* dst = &g_ze[((size_t)((n*H2v + row)*W2v + col))*EMB + e0];
#pragma unroll
        for (int u = 0; u < 8; u++) {
            float f0,f1,f2,f3;
            unpack2(z2[2*u], f0, f1); unpack2(z2[2*u+1], f2, f3);
            *reinterpret_cast<float4*>(dst + 4*u) = make_float4(f0, f1, f2, f3);
        }
    }
}

// ================= VQ WMMA fp16 3-product: argmin + z_st + loss =================
// CTA = 128 px; 16 N-tiles of 64 codes (K=64). block 256 = 8 warps (4m x 2n32).
// smem floats: Ah[0,4608) Al[4608,9216) Bh[9216,11520) Bl[11520,13824)
//              e2s[13824,13888) Cs[13888,22592) widx[22592,22720) lred[22720,22976)
__global__ void __launch_bounds__(256, 2) k_vq_wmma(const float* __restrict__ cb,
                                                    float* __restrict__ dout) {
    extern __shared__ float smf[];
    __half* Ah  = reinterpret_cast<__half*>(smf);           // [128][72]
    __half* Al  = reinterpret_cast<__half*>(smf + 4608);    // [128][72]
    __half* Bh  = reinterpret_cast<__half*>(smf + 9216);    // [64][72]
    __half* Bl  = reinterpret_cast<__half*>(smf + 11520);   // [64][72]
    float* e2s  = smf + 13824;                              // 64
    float* Cs   = smf + 13888;                              // [128][68]
    int*   widx = reinterpret_cast<int*>(smf + 22592);      // 128
    float* lred = smf + 22720;                              // 256

    int tid = threadIdx.x;
    int pb = blockIdx.x * 128;
    int wid = tid >> 5;
    int m0 = (wid & 3) * 32;
    int n0 = (wid >> 2) * 32;

    // stage A: 128 px x 64 dims, split
    for (int i = tid; i < 128*16; i += 256) {
        int px = i >> 4, f4 = i & 15;
        float4 v = *reinterpret_cast<const float4*>(&g_ze[(size_t)(pb + px)*EMB + 4*f4]);
        __half h0 = __float2half(v.x), h1 = __float2half(v.y);
        __half h2 = __float2half(v.z), h3 = __float2half(v.w);
        int o = px*72 + 4*f4;
        Ah[o]   = h0; Al[o]   = __float2half(v.x - __half2float(h0));
        Ah[o+1] = h1; Al[o+1] = __float2half(v.y - __half2float(h1));
        Ah[o+2] = h2; Al[o+2] = __float2half(v.z - __half2float(h2));
        Ah[o+3] = h3; Al[o+3] = __float2half(v.w - __half2float(h3));
    }

    int spx = tid >> 1;          // scan pixel
    int shalf = tid & 1;         // scan half (32 codes)
    float best = 3.4e38f; int bi = 0;

#pragma unroll 1
    for (int nt = 0; nt < 16; nt++) {
        int code0 = nt * 64;
        __syncthreads();
        // stage B: 64 codes x 64 dims (8 uint4 per code)
        for (int i = tid; i < 512; i += 256) {
            int c = i >> 3, c8 = i & 7;
            size_t go = (size_t)(code0 + c)*EMB + 8*c8;
            *reinterpret_cast<uint4*>(&Bh[c*72 + 8*c8]) =
                *reinterpret_cast<const uint4*>(&g_cbh[go]);
            *reinterpret_cast<uint4*>(&Bl[c*72 + 8*c8]) =
                *reinterpret_cast<const uint4*>(&g_cbl[go]);
        }
        if (tid < 64) e2s[tid] = g_e2[code0 + tid];
        __syncthreads();
        wmma::fragment<wmma::accumulator, 16, 16, 16, float> acc[2][2];
#pragma unroll
        for (int im = 0; im < 2; im++)
#pragma unroll
            for (int in = 0; in < 2; in++) wmma::fill_fragment(acc[im][in], 0.0f);
#pragma unroll
        for (int ks = 0; ks < 4; ks++) {
            int kk = ks * 16;
            wmma::fragment<wmma::matrix_a, 16, 16, 16, __half, wmma::row_major> ahf[2], alf[2];
#pragma unroll
            for (int im = 0; im < 2; im++) {
                wmma::load_matrix_sync(ahf[im], &Ah[(m0 + 16*im)*72 + kk], 72);
                wmma::load_matrix_sync(alf[im], &Al[(m0 + 16*im)*72 + kk], 72);
            }
#pragma unroll
            for (int in = 0; in < 2; in++) {
                wmma::fragment<wmma::matrix_b, 16, 16, 16, __half, wmma::col_major> bhf, blf;
                wmma::load_matrix_sync(bhf, &Bh[(n0 + 16*in)*72 + kk], 72);
                wmma::load_matrix_sync(blf, &Bl[(n0 + 16*in)*72 + kk], 72);
#pragma unroll
                for (int im = 0; im < 2; im++) {
                    wmma::mma_sync(acc[im][in], alf[im], bhf, acc[im][in]);
                    wmma::mma_sync(acc[im][in], ahf[im], blf, acc[im][in]);
                    wmma::mma_sync(acc[im][in], ahf[im], bhf, acc[im][in]);
                }
            }
        }
#pragma unroll
        for (int im = 0; im < 2; im++)
#pragma unroll
            for (int in = 0; in < 2; in++)
                wmma::store_matrix_sync(&Cs[(m0 + 16*im)*68 + n0 + 16*in],
                                        acc[im][in], 68, wmma::mem_row_major);
        __syncthreads();
        // scan 32 codes
        const float* cp = &Cs[spx*68 + shalf*32];
        const float* ep = &e2s[shalf*32];
#pragma unroll 8
        for (int c = 0; c < 32; c++) {
            float dist = ep[c] - 2.0f*cp[c];
            if (dist < best) { best = dist; bi = code0 + shalf*32 + c; }
        }
    }
    // combine halves
    {
        float ob = __shfl_xor_sync(0xffffffffu, best, 1);
        int   oi = __shfl_xor_sync(0xffffffffu, bi, 1);
        if (ob < best || (ob == best && oi < bi)) { best = ob; bi = oi; }
        if (shalf == 0) {
            widx[spx] = bi;
            dout[TOK_OFF + pb + spx] = (float)bi;
        }
    }
    __syncthreads();
    // z_st + loss: thread handles (spx, shalf) -> 32 dims
    {
        int idx = widx[spx];
        const float* cq = &cb[(size_t)idx*EMB + shalf*32];
        const float* ze = &g_ze[(size_t)(pb + spx)*EMB + shalf*32];
        __half*      zs = &g_zsth[(size_t)(pb + spx)*EMB + shalf*32];
        float lsum = 0.0f;
#pragma unroll 8
        for (int d = 0; d < 32; d++) {
            float zq = cq[d]; float z = ze[d];
            float diff = zq - z;
            zs[d] = __float2half(z + diff);
            lsum = fmaf(diff, diff, lsum);
        }
        lred[tid] = lsum;
    }
    __syncthreads();
    for (int s = 128; s > 0; s >>= 1) {
        if (tid < s) lred[tid] += lred[tid + s];
        __syncthreads();
    }
    if (tid == 0) atomicAdd(&g_loss, lred[0]);
}

// ================= WMMA fp16 transposed-conv (reg-prefetch pipelined) =====
template<int CI, int HIN, int WIN, bool RGB>
__global__ void __launch_bounds__(256, 2) k_convt_wmma(
    const __half* __restrict__ src, const __half* __restrict__ wt,
    const float* __restrict__ bias,
    const float* __restrict__ w3, const float* __restrict__ b3,
    void* __restrict__ dstv)
{
    constexpr int CIC64 = CI / 64;
    constexpr int NCH   = 4 * CIC64;
    constexpr int HOUT  = 2 * HIN;
    constexpr int WOUT  = 2 * WIN;

    extern __shared__ float smf[];
    __half* As   = reinterpret_cast<__half*>(smf);          // [128][72]
    __half* Bs   = reinterpret_cast<__half*>(smf + 4608);   // [64][136]
    float* Cs    = smf;             // epilogue reuse
    float* biass = smf + 17152;
    float* w3s   = smf + 17280;
    float* b3s   = smf + 17664;

    int tid = threadIdx.x;
    int bx = blockIdx.x, pr = blockIdx.y, n = blockIdx.z;
    int t  = bx & 1;
    int xh = bx >> 1;
    int oy = 4*(pr >> 1) + (pr & 1);
    int x0 = xh * 128;
    int xhalf = x0 >> 1;
    int kyA = oy & 1;
    int iy0 = (oy + kyA - 2) >> 1;

    for (int i = tid; i < 128; i += 256) biass[i] = bias[i];
    if (RGB) {
        for (int i = tid; i < 384; i += 256) w3s[i] = w3[i];
        if (tid < 3) b3s[tid] = b3[tid];
    }

    int wid = tid >> 5;
    int m0 = (wid & 3) * 32;
    int n0 = (wid >> 2) * 64;

    wmma::fragment<wmma::accumulator, 16, 16, 16, float> acc[2][4];
#pragma unroll
    for (int im = 0; im < 2; im++)
#pragma unroll
        for (int in = 0; in < 4; in++) wmma::fill_fragment(acc[im][in], 0.0f);

    uint4 pa[4], pb[4];
    auto ldg_chunk = [&](int c) {
        int kyi = c / (2*CIC64);
        int kxi = (c / CIC64) & 1;
        int ci0 = (c % CIC64) * 64;
        int xb = xhalf + t + kxi - 1;
#pragma unroll
        for (int q = 0; q < 4; q++) {
            int u = tid + q*256;
            int m = u >> 3, c8 = u & 7;
            int h = m >> 6, j = m & 63;
            int y = iy0 + h + kyi;
            int col = xb + j;
            uint4 v = make_uint4(0,0,0,0);
            if (y >= 0 && y < HIN && col >= 0 && col < WIN)
                v = *reinterpret_cast<const uint4*>(
                    &src[((size_t)((n*HIN + y)*WIN + col))*CI + ci0 + 8*c8]);
            pa[q] = v;
        }
        int k0 = ((kyA + 2*kyi)*4 + (t + 2*kxi))*CI + ci0;
#pragma unroll
        for (int q = 0; q < 4; q++) {
            int u = tid + q*256;
            int kk = u >> 4, c16 = u & 15;
            pb[q] = *reinterpret_cast<const uint4*>(&wt[(size_t)(k0 + kk)*128 + 8*c16]);
        }
    };
    auto sts_chunk = [&]() {
#pragma unroll
        for (int q = 0; q < 4; q++) {
            int u = tid + q*256;
            int m = u >> 3, c8 = u & 7;
            *reinterpret_cast<uint4*>(&As[m*72 + 8*c8]) = pa[q];
        }
#pragma unroll
        for (int q = 0; q < 4; q++) {
            int u = tid + q*256;
            int kk = u >> 4, c16 = u & 15;
            *reinterpret_cast<uint4*>(&Bs[kk*136 + 8*c16]) = pb[q];
        }
    };

    ldg_chunk(0);
    sts_chunk();
    __syncthreads();
#pragma unroll 1
    for (int c = 0; c < NCH; c++) {
        if (c + 1 < NCH) ldg_chunk(c + 1);
#pragma unroll
        for (int ks = 0; ks < 4; ks++) {
            int kk = ks * 16;
            wmma::fragment<wmma::matrix_a, 16, 16, 16, __half, wmma::row_major> af[2];
#pragma unroll
            for (int im = 0; im < 2; im++)
                wmma::load_matrix_sync(af[im], &As[(m0 + 16*im)*72 + kk], 72);
#pragma unroll
            for (int in = 0; in < 4; in++) {
                wmma::fragment<wmma::matrix_b, 16, 16, 16, __half, wmma::row_major> bf;
                wmma::load_matrix_sync(bf, &Bs[kk*136 + n0 + 16*in], 136);
#pragma unroll
                for (int im = 0; im < 2; im++)
                    wmma::mma_sync(acc[im][in], af[im], bf, acc[im][in]);
            }
        }
        __syncthreads();
        if (c + 1 < NCH) {
            sts_chunk();
        }
        __syncthreads();
    }
#pragma unroll
    for (int im = 0; im < 2; im++)
#pragma unroll
        for (int in = 0; in < 4; in++)
            wmma::store_matrix_sync(&Cs[(m0 + 16*im)*132 + n0 + 16*in],
                                    acc[im][in], 132, wmma::mem_row_major);
    __syncthreads();
    // epilogue
    {
        int m = tid >> 1;
        int half = tid & 1;
        int h = m >> 6, j = m & 63;
        int row = oy + 2*h;
        int ox = x0 + 2*j + t;
        const float* cp = &Cs[m*132 + half*64];
        if (RGB) {
            float* dst = reinterpret_cast<float*>(dstv);
            float r = 0.0f, g = 0.0f, bl = 0.0f;
#pragma unroll 8
            for (int kk = 0; kk < 64; kk++) {
                int cc = half*64 + kk;
                float gv = gelu_f(cp[kk] + biass[cc]);
                r  = fmaf(gv, w3s[cc*3+0], r);
                g  = fmaf(gv, w3s[cc*3+1], g);
                bl = fmaf(gv, w3s[cc*3+2], bl);
            }
            r  += __shfl_xor_sync(0xffffffffu, r, 1);
            g  += __shfl_xor_sync(0xffffffffu, g, 1);
            bl += __shfl_xor_sync(0xffffffffu, bl, 1);
            if (half == 0) {
                float* dp = dst + ((size_t)((n*HOUT + row)*WOUT + ox))*3;
                dp[0] = r + b3s[0];
                dp[1] = g + b3s[1];
                dp[2] = bl + b3s[2];
            }
        } else {
            __half* dst = reinterpret_cast<__half*>(dstv);
            __half* dp = dst + ((size_t)((n*HOUT + row)*WOUT + ox))*128 + half*64;
#pragma unroll
            for (int k2 = 0; k2 < 32; k2++) {
                float a = gelu_f(cp[2*k2+0] + biass[half*64 + 2*k2+0]);
                float b = gelu_f(cp[2*k2+1] + biass[half*64 + 2*k2+1]);
                *reinterpret_cast<__half2*>(dp + 2*k2) = __floats2half2_rn(a, b);
            }
        }
    }
}

// ================= finalize losses =================
__global__ void k_final(float* __restrict__ dout) {
    float l = g_loss / (float)(TOK_ELEMS * EMB);
    dout[LOSS_OFF]     = l;
    dout[LOSS_OFF + 1] = l;
}

// ================= launch =================
extern "C" void kernel_launch(void* const* d_in, const int* in_sizes, int n_in,
                              void* d_out, int out_size) {
    const float* x      = (const float*)d_in[0];
    const float* enc_w1 = (const float*)d_in[1];
    const float* enc_b1 = (const float*)d_in[2];
    const float* enc_w2 = (const float*)d_in[3];
    const float* enc_b2 = (const float*)d_in[4];
    const float* enc_w3 = (const float*)d_in[5];
    const float* enc_b3 = (const float*)d_in[6];
    const float* cb     = (const float*)d_in[7];
    const float* dec_w1 = (const float*)d_in[8];
    const float* dec_b1 = (const float*)d_in[9];
    const float* dec_w2 = (const float*)d_in[10];
    const float* dec_b2 = (const float*)d_in[11];
    const float* dec_w3 = (const float*)d_in[12];
    const float* dec_b3 = (const float*)d_in[13];
    float* out = (float*)d_out;

    __half* wt1p; cudaGetSymbolAddress((void**)&wt1p, g_wt1h);
    __half* wt2p; cudaGetSymbolAddress((void**)&wt2p, g_wt2h);
    __half* zstp; cudaGetSymbolAddress((void**)&zstp, g_zsth);
    __half* g1p;  cudaGetSymbolAddress((void**)&g1p, g_g1h);
    __half* w2hp; cudaGetSymbolAddress((void**)&w2hp, g_w2hh);
    __half* w2lp; cudaGetSymbolAddress((void**)&w2lp, g_w2ll);
    __half* cbhp; cudaGetSymbolAddress((void**)&cbhp, g_cbh);
    __half* cblp; cudaGetSymbolAddress((void**)&cblp, g_cbl);

    const int smem_dec = 17667 * 4;   // 70668 B (occ 2)
    const int smem_c2  = 18112 * 4;   // 72448 B (occ 2)
    const int smem_c1  = 17024 * 4;   // 68096 B (occ 2)
    const int smem_vq  = 22976 * 4;   // 91904 B (occ 2)
    static int smem_set = 0;
    if (!smem_set) {
        cudaFuncSetAttribute(k_convt_wmma<64, 64, 64, false>,
                             cudaFuncAttributeMaxDynamicSharedMemorySize, smem_dec);
        cudaFuncSetAttribute(k_convt_wmma<128, 128, 128, true>,
                             cudaFuncAttributeMaxDynamicSharedMemorySize, smem_dec);
        cudaFuncSetAttribute(k_conv2_wmma,
                             cudaFuncAttributeMaxDynamicSharedMemorySize, smem_c2);
        cudaFuncSetAttribute(k_conv1_wmma,
                             cudaFuncAttributeMaxDynamicSharedMemorySize, smem_c1);
        cudaFuncSetAttribute(k_vq_wmma,
                             cudaFuncAttributeMaxDynamicSharedMemorySize, smem_vq);
        smem_set = 1;
    }

    k_zero_loss<<<1, 1>>>();
    k_prep_half<<<512, 256>>>(dec_w1, wt1p, 131072);
    k_prep_half<<<1024, 256>>>(dec_w2, wt2p, 262144);
    k_prep_half_split<<<1024, 256>>>(enc_w2, w2hp, w2lp, 262144);
    k_prep_half_split<<<256, 256>>>(cb, cbhp, cblp, 65536);
    k_prep_e2<<<4, 256>>>(cb);

    k_conv1_wmma<<<dim3(128, 16), 256, smem_c1>>>(x, enc_w1, enc_b1);
    k_conv2_wmma<<<dim3(32, 16), 256, smem_c2>>>(enc_b2, enc_w3, enc_b3);
    k_vq_wmma<<<512, 256, smem_vq>>>(cb, out);

    k_convt_wmma<64, 64, 64, false><<<dim3(2, 64, 16), 256, smem_dec>>>(
        zstp, wt1p, dec_b1, nullptr, nullptr, g1p);
    k_convt_wmma<128, 128, 128, true><<<dim3(4, 128, 16), 256, smem_dec>>>(
        g1p, wt2p, dec_b2, dec_w3, dec_b3, out);
    k_final<<<1, 1>>>(out);
}